// round 12
// baseline (speedup 1.0000x reference)
#include <cuda_runtime.h>
#include <math.h>
#include <stdint.h>

#define MAXN 50048
#define MAXE 800000

// ---------------- scratch (device globals; no allocation allowed) ----------
__device__ __align__(128) float g_h[MAXN * 256];
__device__ __align__(128) float g_skip[MAXN * 256];
__device__ __align__(128) float g_hw[MAXN * 256];
__device__ __align__(128) float g_p[MAXN * 256];
__device__ __align__(128) float g_f1[MAXN * 512];   // also layer-0 packed hw|p
__device__ __align__(128) float g_logits[MAXN * 64];
__device__ __align__(128) float g_dinv[MAXN];
__device__ __align__(128) int   g_degi[MAXN];       // zero-init; re-zeroed each run
__device__ __align__(128) int   g_rowptr[MAXN + 1];
__device__ __align__(128) int   g_cursor[MAXN];
__device__ __align__(128) int   g_esrc[MAXE];
__device__ __align__(128) float g_enorm[MAXE];
__device__ __align__(128) float g_wt[524288];       // all transposed weights (2 MB)

// ---------------- helpers --------------------------------------------------
__device__ __forceinline__ float gelu_exact(float x) {
    return 0.5f * x * (1.0f + erff(x * 0.70710678118654752440f));
}
__device__ __forceinline__ void mma_tf32(float* c, const uint32_t* a, const uint32_t* b) {
    asm("mma.sync.aligned.m16n8k8.row.col.f32.tf32.tf32.f32 "
        "{%0,%1,%2,%3},{%4,%5,%6,%7},{%8,%9},{%0,%1,%2,%3};"
        : "+f"(c[0]), "+f"(c[1]), "+f"(c[2]), "+f"(c[3])
        : "r"(a[0]), "r"(a[1]), "r"(a[2]), "r"(a[3]), "r"(b[0]), "r"(b[1]));
}
__device__ __forceinline__ void ldsm_x4(uint32_t* r, uint32_t saddr) {
    asm volatile("ldmatrix.sync.aligned.m8n8.x4.shared.b16 {%0,%1,%2,%3}, [%4];"
                 : "=r"(r[0]), "=r"(r[1]), "=r"(r[2]), "=r"(r[3]) : "r"(saddr));
}
__device__ __forceinline__ void ldsm_x2(uint32_t* r, uint32_t saddr) {
    asm volatile("ldmatrix.sync.aligned.m8n8.x2.shared.b16 {%0,%1}, [%2];"
                 : "=r"(r[0]), "=r"(r[1]) : "r"(saddr));
}
__device__ __forceinline__ void cp16(void* dst, const void* src, int bytes) {
    uint32_t d = (uint32_t)__cvta_generic_to_shared(dst);
    asm volatile("cp.async.cg.shared.global [%0], [%1], 16, %2;"
                 :: "r"(d), "l"(src), "r"(bytes));
}
__device__ __forceinline__ void cp_commit() { asm volatile("cp.async.commit_group;"); }
template <int N>
__device__ __forceinline__ void cp_wait() { asm volatile("cp.async.wait_group %0;" :: "n"(N)); }

// ---------------- fused preprocessing #1: degree count + weight transpose --
// Blocks [0, cblocks) count degrees (degi must be zero on entry; it is:
// zero-init at module load, re-zeroed by k_scan_all each run).
// Blocks [cblocks, cblocks+total_tiles) transpose one 32x32 weight tile each.
struct TransArgs {
    const float* W[9];
    long long    woff[9];
    int K[9];
    int N[9];
    int tiles[9];
};
__global__ void k_count_transpose(TransArgs a, float* wt, int* degi,
                                  const int* __restrict__ dst, int e, int cblocks) {
    if ((int)blockIdx.x < cblocks) {
        int i = blockIdx.x * 256 + threadIdx.x;
        if (i < e) atomicAdd(&degi[dst[i]], 1);
        return;
    }
    __shared__ float tile[32][33];
    int t = blockIdx.x - cblocks;
    int m = 0;
    while (t >= a.tiles[m]) { t -= a.tiles[m]; m++; }
    int K = a.K[m], N = a.N[m];
    int ntx = N >> 5;
    int k0 = (t / ntx) * 32, n0 = (t % ntx) * 32;
    const float* W = a.W[m];
    float* Wt = wt + a.woff[m];
    int tx = threadIdx.x & 31, ty = threadIdx.x >> 5;   // 32 x 8
    for (int i = ty; i < 32; i += 8)
        tile[i][tx] = W[(size_t)(k0 + i) * N + n0 + tx];
    __syncthreads();
    for (int i = ty; i < 32; i += 8)
        Wt[(size_t)(n0 + i) * K + k0 + tx] = tile[tx][i];
}

// ---------------- preprocessing #2: fused scan + dinv (+ re-zero degi) -----
__global__ void __launch_bounds__(1024) k_scan_all(
    int* __restrict__ deg, float* __restrict__ dinv,
    int* __restrict__ rowptr, int* __restrict__ cursor, int n, int e) {
    __shared__ int sh[1024];
    int t = threadIdx.x;
    int per = (n + 1023) >> 10;
    int lo = t * per, hi = min(lo + per, n);
    int sum = 0;
    for (int i = lo; i < hi; i++) sum += deg[i];
    sh[t] = sum;
    __syncthreads();
    for (int o = 1; o < 1024; o <<= 1) {
        int u = (t >= o) ? sh[t - o] : 0;
        __syncthreads();
        sh[t] += u;
        __syncthreads();
    }
    int off = sh[t] - sum;
    for (int i = lo; i < hi; i++) {
        int d = deg[i];
        deg[i] = 0;                    // restore zeros for next graph replay
        rowptr[i] = off;
        cursor[i] = off;
        dinv[i] = rsqrtf((float)d + 1.0f);
        off += d;
    }
    if (t == 0) rowptr[n] = e;
}

// ---------------- preprocessing #3: bucket edges by dst --------------------
__global__ void k_bucket(const int* __restrict__ src, const int* __restrict__ dst,
                         const float* __restrict__ dinv, int* __restrict__ cursor,
                         int* __restrict__ esrc, float* __restrict__ enorm, int e) {
    int i = blockIdx.x * blockDim.x + threadIdx.x;
    if (i < e) {
        int s = src[i], d = dst[i];
        int pos = atomicAdd(&cursor[d], 1);
        esrc[pos] = s;
        enorm[pos] = dinv[s] * dinv[d];
    }
}

// ---------------- BIG TF32 GEMM: 128x128 tile, 2-stage, ldmatrix -----------
// C[M,N] = A[M,K] @ Bt^T, Bt is [N][K] k-contiguous. N%128==0, K%32==0.
// 8 warps: 4 in M x 2 in N, warp tile 32x64. 2 CTAs/SM.
// MODE: 0 raw, 1 +bias+addmat, 2 gelu(x+bias)
#define BPITCH 36
#define BIG_A_STAGE (128 * BPITCH)
#define BIG_B_STAGE (128 * BPITCH)
#define BIG_STAGE   (BIG_A_STAGE + BIG_B_STAGE)
#define BIG_SMEM_BYTES (2 * BIG_STAGE * 4)   // 73728

template <int MODE>
__global__ void __launch_bounds__(256, 2) sgemm_big(
    const float* __restrict__ A, const float* __restrict__ Bt, float* __restrict__ C,
    int M, int K, int N, const float* __restrict__ bias, const float* __restrict__ add) {
    extern __shared__ float smem[];
    const uint32_t smem_u32 = (uint32_t)__cvta_generic_to_shared(smem);

    const int tid  = threadIdx.x;
    const int lane = tid & 31;
    const int wid  = tid >> 5;
    const int wm = wid & 3, wn = wid >> 2;
    const int gid = lane >> 2, tig = lane & 3;
    const int row0 = blockIdx.y * 128;
    const int col0 = blockIdx.x * 128;

    const int lr[4] = {(tid + 0) >> 3, (tid + 256) >> 3, (tid + 512) >> 3, (tid + 768) >> 3};
    const int lk = (tid & 7) * 4;

    const int k_tiles = K >> 5;

    auto load_stage = [&](int s, int k0) {
        float* as = smem + s * BIG_STAGE;
        float* bs = as + BIG_A_STAGE;
        #pragma unroll
        for (int i = 0; i < 4; i++) {
            int row = lr[i];
            int grow = row0 + row;
            int ok = (grow < M) ? 16 : 0;
            if (!ok) grow = M - 1;
            cp16(&as[row * BPITCH + lk], &A[(size_t)grow * K + k0 + lk], ok);
        }
        #pragma unroll
        for (int i = 0; i < 4; i++) {
            int n = lr[i];
            cp16(&bs[n * BPITCH + lk], &Bt[(size_t)(col0 + n) * K + k0 + lk], 16);
        }
    };

    const int a_i = lane & 7, a_t = lane >> 3;
    const uint32_t a_off = ((uint32_t)((wm * 32 + a_i + ((a_t & 1) << 3)) * BPITCH
                                       + ((a_t >> 1) << 2))) * 4u;
    const int b_i = lane & 7, b_t = (lane >> 3) & 1;
    const uint32_t b_off = ((uint32_t)((wn * 64 + b_i) * BPITCH + (b_t << 2))) * 4u;

    float acc[2][8][4];
    #pragma unroll
    for (int i = 0; i < 2; i++)
        #pragma unroll
        for (int j = 0; j < 8; j++)
            #pragma unroll
            for (int k = 0; k < 4; k++) acc[i][j][k] = 0.0f;

    load_stage(0, 0);
    cp_commit();

    for (int t = 0; t < k_tiles; t++) {
        cp_wait<0>();
        __syncthreads();
        const int st = t & 1;
        if (t + 1 < k_tiles) {
            load_stage((t + 1) & 1, (t + 1) * 32);
        }
        cp_commit();

        const uint32_t as_base = smem_u32 + (uint32_t)(st * BIG_STAGE) * 4u;
        const uint32_t bs_base = as_base + (uint32_t)BIG_A_STAGE * 4u;

        #pragma unroll
        for (int kb = 0; kb < 32; kb += 8) {
            uint32_t af[2][4], bf[8][2];
            #pragma unroll
            for (int mt = 0; mt < 2; mt++)
                ldsm_x4(af[mt], as_base + a_off + (uint32_t)(mt * 16 * BPITCH + kb) * 4u);
            #pragma unroll
            for (int nt = 0; nt < 8; nt++)
                ldsm_x2(bf[nt], bs_base + b_off + (uint32_t)(nt * 8 * BPITCH + kb) * 4u);
            #pragma unroll
            for (int mt = 0; mt < 2; mt++)
                #pragma unroll
                for (int nt = 0; nt < 8; nt++)
                    mma_tf32(acc[mt][nt], af[mt], bf[nt]);
        }
    }

    #pragma unroll
    for (int mt = 0; mt < 2; mt++) {
        #pragma unroll
        for (int half = 0; half < 2; half++) {
            int row = row0 + wm * 32 + mt * 16 + gid + half * 8;
            if (row >= M) continue;
            #pragma unroll
            for (int nt = 0; nt < 8; nt++) {
                int col = col0 + wn * 64 + nt * 8 + tig * 2;
                float v0 = acc[mt][nt][half * 2 + 0];
                float v1 = acc[mt][nt][half * 2 + 1];
                size_t o = (size_t)row * N + col;
                if (MODE == 1) {
                    v0 += bias[col]     + add[o];
                    v1 += bias[col + 1] + add[o + 1];
                } else if (MODE == 2) {
                    v0 = gelu_exact(v0 + bias[col]);
                    v1 = gelu_exact(v1 + bias[col + 1]);
                }
                *(float2*)&C[o] = make_float2(v0, v1);
            }
        }
    }
}

// ---------------- SMALL TF32 GEMM (N=64 logits), 3-stage, ldmatrix ---------
#define S_STAGES 3
#define S_A_STAGE (128 * BPITCH)
#define S_B_STAGE (64 * BPITCH)
#define S_SMEM_BYTES (S_STAGES * (S_A_STAGE + S_B_STAGE) * 4)   // 82944

__global__ void __launch_bounds__(256) sgemm_small(
    const float* __restrict__ A, const float* __restrict__ Bt, float* __restrict__ C,
    int M, int K, int N) {
    extern __shared__ float smem[];
    const uint32_t smem_u32 = (uint32_t)__cvta_generic_to_shared(smem);

    const int tid  = threadIdx.x;
    const int lane = tid & 31;
    const int wid  = tid >> 5;
    const int wm = wid & 3, wn = wid >> 2;
    const int gid = lane >> 2, tig = lane & 3;
    const int row0 = blockIdx.y * 128;
    const int col0 = 0;

    const int ar[4] = {(tid + 0) >> 3, (tid + 256) >> 3, (tid + 512) >> 3, (tid + 768) >> 3};
    const int ak = (tid & 7) * 4;
    const int bn[2] = {(tid + 0) >> 3, (tid + 256) >> 3};
    const int bk = (tid & 7) * 4;

    const int k_tiles = K >> 5;

    auto load_stage = [&](int s, int k0) {
        float* as = smem + s * S_A_STAGE;
        float* bs = smem + S_STAGES * S_A_STAGE + s * S_B_STAGE;
        #pragma unroll
        for (int i = 0; i < 4; i++) {
            int row = ar[i];
            int grow = row0 + row;
            int ok = (grow < M) ? 16 : 0;
            if (!ok) grow = M - 1;
            cp16(&as[row * BPITCH + ak], &A[(size_t)grow * K + k0 + ak], ok);
        }
        #pragma unroll
        for (int i = 0; i < 2; i++) {
            int n = bn[i];
            cp16(&bs[n * BPITCH + bk], &Bt[(size_t)(col0 + n) * K + k0 + bk], 16);
        }
    };

    const int a_i = lane & 7, a_t = lane >> 3;
    const uint32_t a_off = ((uint32_t)((wm * 32 + a_i + ((a_t & 1) << 3)) * BPITCH
                                       + ((a_t >> 1) << 2))) * 4u;
    const int b_i = lane & 7, b_t = (lane >> 3) & 1;
    const uint32_t b_off = ((uint32_t)((wn * 32 + b_i) * BPITCH + (b_t << 2))) * 4u;

    float acc[2][4][4];
    #pragma unroll
    for (int i = 0; i < 2; i++)
        #pragma unroll
        for (int j = 0; j < 4; j++)
            #pragma unroll
            for (int k = 0; k < 4; k++) acc[i][j][k] = 0.0f;

    #pragma unroll
    for (int s = 0; s < S_STAGES - 1; s++) {
        if (s < k_tiles) load_stage(s, s * 32);
        cp_commit();
    }

    for (int t = 0; t < k_tiles; t++) {
        cp_wait<S_STAGES - 2>();
        __syncthreads();
        const int st = t % S_STAGES;
        const uint32_t as_base = smem_u32 + (uint32_t)(st * S_A_STAGE) * 4u;
        const uint32_t bs_base = smem_u32 + (uint32_t)(S_STAGES * S_A_STAGE + st * S_B_STAGE) * 4u;

        #pragma unroll
        for (int kb = 0; kb < 32; kb += 8) {
            uint32_t af[2][4], bf[4][2];
            #pragma unroll
            for (int mt = 0; mt < 2; mt++)
                ldsm_x4(af[mt], as_base + a_off + (uint32_t)(mt * 16 * BPITCH + kb) * 4u);
            #pragma unroll
            for (int nt = 0; nt < 4; nt++)
                ldsm_x2(bf[nt], bs_base + b_off + (uint32_t)(nt * 8 * BPITCH + kb) * 4u);
            #pragma unroll
            for (int mt = 0; mt < 2; mt++)
                #pragma unroll
                for (int nt = 0; nt < 4; nt++)
                    mma_tf32(acc[mt][nt], af[mt], bf[nt]);
        }

        int nt2 = t + S_STAGES - 1;
        if (nt2 < k_tiles) load_stage(nt2 % S_STAGES, nt2 * 32);
        cp_commit();
    }

    #pragma unroll
    for (int mt = 0; mt < 2; mt++) {
        #pragma unroll
        for (int half = 0; half < 2; half++) {
            int row = row0 + wm * 32 + mt * 16 + gid + half * 8;
            if (row >= M) continue;
            #pragma unroll
            for (int nt = 0; nt < 4; nt++) {
                int col = col0 + wn * 32 + nt * 8 + tig * 2;
                size_t o = (size_t)row * N + col;
                *(float2*)&C[o] = make_float2(acc[mt][nt][half * 2 + 0],
                                              acc[mt][nt][half * 2 + 1]);
            }
        }
    }
}

// ---------------- fused gather + conv-epilogue + LN + GELU (float4) --------
// hw/pp row strides parameterized (layer 0 reads the packed [N,512] buffer).
__global__ void __launch_bounds__(256) gcn_post(
    const float* __restrict__ hw, int hw_stride,
    const float* __restrict__ pp, int pp_stride,
    const int* __restrict__ rowptr, const int* __restrict__ esrc,
    const float* __restrict__ enorm, const float* __restrict__ dinv,
    const float* __restrict__ bcv, const float* __restrict__ bpv,
    const float* __restrict__ gv, const float* __restrict__ bev,
    float* __restrict__ skip_out, float* __restrict__ h_out) {
    int r = blockIdx.x;
    int tid = threadIdx.x;
    int g = tid & 63;
    int e = tid >> 6;
    int lane = tid & 31;
    int warp = tid >> 5;
    int beg = rowptr[r], end = rowptr[r + 1];

    float4 acc = make_float4(0.f, 0.f, 0.f, 0.f);
    for (int j = beg + e; j < end; j += 4) {
        int s = __ldg(&esrc[j]);
        float w = __ldg(&enorm[j]);
        const float4 v = *(const float4*)&hw[(size_t)s * hw_stride + g * 4];
        acc.x = fmaf(v.x, w, acc.x);
        acc.y = fmaf(v.y, w, acc.y);
        acc.z = fmaf(v.z, w, acc.z);
        acc.w = fmaf(v.w, w, acc.w);
    }
    __shared__ float4 sacc[256];
    sacc[tid] = acc;
    __syncthreads();

    float4 t = make_float4(0.f, 0.f, 0.f, 0.f);
    float partial = 0.f;
    size_t baseo = (size_t)r * 256 + g * 4;
    if (tid < 64) {
        float4 a0 = sacc[g], a1 = sacc[g + 64], a2 = sacc[g + 128], a3 = sacc[g + 192];
        float ax = a0.x + a1.x + a2.x + a3.x;
        float ay = a0.y + a1.y + a2.y + a3.y;
        float az = a0.z + a1.z + a2.z + a3.z;
        float aw = a0.w + a1.w + a2.w + a3.w;
        float di = dinv[r];
        float d2 = di * di;
        float4 hv = *(const float4*)&hw[(size_t)r * hw_stride + g * 4];
        float4 pv = *(const float4*)&pp[(size_t)r * pp_stride + g * 4];
        float4 bc4 = *(const float4*)&bcv[g * 4];
        float4 bp4 = *(const float4*)&bpv[g * 4];
        t.x = ax + d2 * hv.x + bc4.x + pv.x + bp4.x;
        t.y = ay + d2 * hv.y + bc4.y + pv.y + bp4.y;
        t.z = az + d2 * hv.z + bc4.z + pv.z + bp4.z;
        t.w = aw + d2 * hv.w + bc4.w + pv.w + bp4.w;
        *(float4*)&skip_out[baseo] = t;
        partial = t.x + t.y + t.z + t.w;
    }

    __shared__ float red[8];
    float s = partial;
    #pragma unroll
    for (int o = 16; o > 0; o >>= 1) s += __shfl_xor_sync(0xffffffffu, s, o);
    if (lane == 0) red[warp] = s;
    __syncthreads();
    float m = 0.f;
    #pragma unroll
    for (int i = 0; i < 8; i++) m += red[i];
    m *= (1.0f / 256.0f);
    __syncthreads();

    float vpart = 0.f;
    float dx = 0.f, dy = 0.f, dz = 0.f, dw = 0.f;
    if (tid < 64) {
        dx = t.x - m; dy = t.y - m; dz = t.z - m; dw = t.w - m;
        vpart = dx * dx + dy * dy + dz * dz + dw * dw;
    }
    float sv = vpart;
    #pragma unroll
    for (int o = 16; o > 0; o >>= 1) sv += __shfl_xor_sync(0xffffffffu, sv, o);
    if (lane == 0) red[warp] = sv;
    __syncthreads();
    float var = 0.f;
    #pragma unroll
    for (int i = 0; i < 8; i++) var += red[i];
    var *= (1.0f / 256.0f);

    if (tid < 64) {
        float rs = rsqrtf(var + 1e-5f);
        float4 g4 = *(const float4*)&gv[g * 4];
        float4 b4 = *(const float4*)&bev[g * 4];
        float4 y;
        y.x = gelu_exact(dx * rs * g4.x + b4.x);
        y.y = gelu_exact(dy * rs * g4.y + b4.y);
        y.z = gelu_exact(dz * rs * g4.z + b4.z);
        y.w = gelu_exact(dw * rs * g4.w + b4.w);
        *(float4*)&h_out[baseo] = y;
    }
}

// ---------------- log-softmax over 64 logits -------------------------------
__global__ void k_logsoftmax(const float* __restrict__ logits, const float* __restrict__ bf2,
                             float* __restrict__ out, int Nn) {
    int r = blockIdx.x * 8 + (threadIdx.x >> 5);
    int lane = threadIdx.x & 31;
    if (r >= Nn) return;
    float v0 = logits[(size_t)r * 64 + lane]      + bf2[lane];
    float v1 = logits[(size_t)r * 64 + 32 + lane] + bf2[32 + lane];
    float mx = fmaxf(v0, v1);
    #pragma unroll
    for (int o = 16; o > 0; o >>= 1) mx = fmaxf(mx, __shfl_xor_sync(0xffffffffu, mx, o));
    float s = expf(v0 - mx) + expf(v1 - mx);
    #pragma unroll
    for (int o = 16; o > 0; o >>= 1) s += __shfl_xor_sync(0xffffffffu, s, o);
    float ls = logf(s);
    out[(size_t)r * 64 + lane]      = v0 - mx - ls;
    out[(size_t)r * 64 + 32 + lane] = v1 - mx - ls;
}

// ---------------- launch ---------------------------------------------------
extern "C" void kernel_launch(void* const* d_in, const int* in_sizes, int n_in,
                              void* d_out, int out_size) {
    const float* x  = (const float*)d_in[0];
    const int*   ei = (const int*)d_in[1];
    int E  = in_sizes[1] / 2;
    int Nn = in_sizes[0] / 128;
    const int* src = ei;
    const int* dst = ei + E;

    const float* Wc[3] = {(const float*)d_in[2],  (const float*)d_in[8],  (const float*)d_in[14]};
    const float* bc[3] = {(const float*)d_in[3],  (const float*)d_in[9],  (const float*)d_in[15]};
    const float* Wp[3] = {(const float*)d_in[4],  (const float*)d_in[10], (const float*)d_in[16]};
    const float* bp[3] = {(const float*)d_in[5],  (const float*)d_in[11], (const float*)d_in[17]};
    const float* gg[3] = {(const float*)d_in[6],  (const float*)d_in[12], (const float*)d_in[18]};
    const float* be[3] = {(const float*)d_in[7],  (const float*)d_in[13], (const float*)d_in[19]};
    const float* W_in = (const float*)d_in[20];
    const float* b_in = (const float*)d_in[21];
    const float* Wf1  = (const float*)d_in[22];
    const float* bf1  = (const float*)d_in[23];
    const float* Wf2  = (const float*)d_in[24];
    const float* bf2  = (const float*)d_in[25];
    float* out = (float*)d_out;

    cudaFuncSetAttribute(sgemm_big<0>, cudaFuncAttributeMaxDynamicSharedMemorySize, BIG_SMEM_BYTES);
    cudaFuncSetAttribute(sgemm_big<1>, cudaFuncAttributeMaxDynamicSharedMemorySize, BIG_SMEM_BYTES);
    cudaFuncSetAttribute(sgemm_big<2>, cudaFuncAttributeMaxDynamicSharedMemorySize, BIG_SMEM_BYTES);
    cudaFuncSetAttribute(sgemm_small,  cudaFuncAttributeMaxDynamicSharedMemorySize, S_SMEM_BYTES);

    float *pH, *pSkip, *pHw, *pP, *pF1, *pLog, *pDinv, *pEn, *pWt;
    int *pDegi, *pRp, *pCur, *pEs;
    cudaGetSymbolAddress((void**)&pH,    g_h);
    cudaGetSymbolAddress((void**)&pSkip, g_skip);
    cudaGetSymbolAddress((void**)&pHw,   g_hw);
    cudaGetSymbolAddress((void**)&pP,    g_p);
    cudaGetSymbolAddress((void**)&pF1,   g_f1);
    cudaGetSymbolAddress((void**)&pLog,  g_logits);
    cudaGetSymbolAddress((void**)&pDinv, g_dinv);
    cudaGetSymbolAddress((void**)&pDegi, g_degi);
    cudaGetSymbolAddress((void**)&pRp,   g_rowptr);
    cudaGetSymbolAddress((void**)&pCur,  g_cursor);
    cudaGetSymbolAddress((void**)&pEs,   g_esrc);
    cudaGetSymbolAddress((void**)&pEn,   g_enorm);
    cudaGetSymbolAddress((void**)&pWt,   g_wt);

    // Transposed-weight layout (floats):
    //   [0]       Wc0 -> rows 0-255 of packed layer-0 [512][128]
    //   [32768]   Wp0 -> rows 256-511 of same region
    //   [65536]   Wc1   [131072] Wp1   [196608] Wc2   [262144] Wp2
    //   [327680]  W_in  [360448] Wf1   [491520] Wf2
    TransArgs ta;
    const float* Ws[9] = {Wc[0], Wp[0], Wc[1], Wp[1], Wc[2], Wp[2], W_in, Wf1, Wf2};
    int Ks[9]  = {128, 128, 256, 256, 256, 256, 128, 256, 512};
    int Nss[9] = {256, 256, 256, 256, 256, 256, 256, 512, 64};
    long long woff[9] = {0, 32768, 65536, 131072, 196608, 262144, 327680, 360448, 491520};
    int total_tiles = 0;
    for (int i = 0; i < 9; i++) {
        ta.W[i] = Ws[i];
        ta.K[i] = Ks[i];
        ta.N[i] = Nss[i];
        ta.woff[i] = woff[i];
        ta.tiles[i] = (Ks[i] >> 5) * (Nss[i] >> 5);
        total_tiles += ta.tiles[i];
    }

    // --- preprocessing: 3 kernels, so the first GEMM is launch #4 (profiled) ---
    int cblocks = (E + 255) / 256;
    k_count_transpose<<<cblocks + total_tiles, 256>>>(ta, pWt, pDegi, dst, E, cblocks);
    k_scan_all<<<1, 1024>>>(pDegi, pDinv, pRp, pCur, Nn, E);
    k_bucket<<<(E + 255) / 256, 256>>>(src, dst, pDinv, pCur, pEs, pEn, E);

    int gy = (Nn + 127) / 128;

    // --- layer 0: single packed GEMM (h == skip == x): [Nn,512] = x @ [Wc0|Wp0] ---
    sgemm_big<0><<<dim3(4, gy), 256, BIG_SMEM_BYTES>>>(x, pWt, pF1, Nn, 128, 512, nullptr, nullptr);
    gcn_post<<<Nn, 256>>>(pF1, 512, pF1 + 256, 512, pRp, pEs, pEn, pDinv,
                          bc[0], bp[0], gg[0], be[0], pSkip, pH);

    // --- layers 1, 2 ---
    for (int l = 1; l < 3; l++) {
        sgemm_big<0><<<dim3(2, gy), 256, BIG_SMEM_BYTES>>>(pH,    pWt + woff[2 * l],     pHw, Nn, 256, 256, nullptr, nullptr);
        sgemm_big<0><<<dim3(2, gy), 256, BIG_SMEM_BYTES>>>(pSkip, pWt + woff[2 * l + 1], pP,  Nn, 256, 256, nullptr, nullptr);
        gcn_post<<<Nn, 256>>>(pHw, 256, pP, 256, pRp, pEs, pEn, pDinv,
                              bc[l], bp[l], gg[l], be[l], pSkip, pH);
    }

    // --- long residual (fused epilogue) + MLP head ---
    sgemm_big<1><<<dim3(2, gy), 256, BIG_SMEM_BYTES>>>(x, pWt + woff[6], pHw, Nn, 128, 256, b_in, pH);
    sgemm_big<2><<<dim3(4, gy), 256, BIG_SMEM_BYTES>>>(pHw, pWt + woff[7], pF1, Nn, 256, 512, bf1, nullptr);
    sgemm_small<<<dim3(1, gy), 256, S_SMEM_BYTES>>>(pF1, pWt + woff[8], pLog, Nn, 512, 64);
    k_logsoftmax<<<(Nn + 7) / 8, 256>>>(pLog, bf2, out, Nn);
}

// round 13
// speedup vs baseline: 1.0070x; 1.0070x over previous
#include <cuda_runtime.h>
#include <math.h>
#include <stdint.h>

#define MAXN 50048
#define MAXE 800000

// ---------------- scratch (device globals; no allocation allowed) ----------
__device__ __align__(128) float g_h[MAXN * 256];
__device__ __align__(128) float g_skip[MAXN * 256];
__device__ __align__(128) float g_hw[MAXN * 256];
__device__ __align__(128) float g_p[MAXN * 256];
__device__ __align__(128) float g_f1[MAXN * 512];
__device__ __align__(128) float g_logits[MAXN * 64];
__device__ __align__(128) float g_dinv[MAXN];
__device__ __align__(128) int   g_degi[MAXN];       // zero-init; re-zeroed each run
__device__ __align__(128) int   g_rowptr[MAXN + 1];
__device__ __align__(128) int   g_cursor[MAXN];
__device__ __align__(128) int   g_esrc[MAXE];
__device__ __align__(128) float g_enorm[MAXE];
__device__ __align__(128) float g_wt[524288];       // all transposed weights (2 MB)

// ---------------- helpers --------------------------------------------------
__device__ __forceinline__ float gelu_exact(float x) {
    return 0.5f * x * (1.0f + erff(x * 0.70710678118654752440f));
}
__device__ __forceinline__ void mma_tf32(float* c, const uint32_t* a, const uint32_t* b) {
    asm("mma.sync.aligned.m16n8k8.row.col.f32.tf32.tf32.f32 "
        "{%0,%1,%2,%3},{%4,%5,%6,%7},{%8,%9},{%0,%1,%2,%3};"
        : "+f"(c[0]), "+f"(c[1]), "+f"(c[2]), "+f"(c[3])
        : "r"(a[0]), "r"(a[1]), "r"(a[2]), "r"(a[3]), "r"(b[0]), "r"(b[1]));
}
__device__ __forceinline__ void ldsm_x4(uint32_t* r, uint32_t saddr) {
    asm volatile("ldmatrix.sync.aligned.m8n8.x4.shared.b16 {%0,%1,%2,%3}, [%4];"
                 : "=r"(r[0]), "=r"(r[1]), "=r"(r[2]), "=r"(r[3]) : "r"(saddr));
}
__device__ __forceinline__ void ldsm_x2(uint32_t* r, uint32_t saddr) {
    asm volatile("ldmatrix.sync.aligned.m8n8.x2.shared.b16 {%0,%1}, [%2];"
                 : "=r"(r[0]), "=r"(r[1]) : "r"(saddr));
}
__device__ __forceinline__ void cp16(void* dst, const void* src, int bytes) {
    uint32_t d = (uint32_t)__cvta_generic_to_shared(dst);
    asm volatile("cp.async.cg.shared.global [%0], [%1], 16, %2;"
                 :: "r"(d), "l"(src), "r"(bytes));
}
__device__ __forceinline__ void cp_commit() { asm volatile("cp.async.commit_group;"); }
template <int N>
__device__ __forceinline__ void cp_wait() { asm volatile("cp.async.wait_group %0;" :: "n"(N)); }

// ---------------- fused preprocessing #1: degree count + weight transpose --
struct TransArgs {
    const float* W[9];
    long long    woff[9];
    int K[9];
    int N[9];
    int tiles[9];
};
__global__ void k_count_transpose(TransArgs a, float* wt, int* degi,
                                  const int* __restrict__ dst, int e, int cblocks) {
    if ((int)blockIdx.x < cblocks) {
        int i = blockIdx.x * 256 + threadIdx.x;
        if (i < e) atomicAdd(&degi[dst[i]], 1);
        return;
    }
    __shared__ float tile[32][33];
    int t = blockIdx.x - cblocks;
    int m = 0;
    while (t >= a.tiles[m]) { t -= a.tiles[m]; m++; }
    int K = a.K[m], N = a.N[m];
    int ntx = N >> 5;
    int k0 = (t / ntx) * 32, n0 = (t % ntx) * 32;
    const float* W = a.W[m];
    float* Wt = wt + a.woff[m];
    int tx = threadIdx.x & 31, ty = threadIdx.x >> 5;   // 32 x 8
    for (int i = ty; i < 32; i += 8)
        tile[i][tx] = W[(size_t)(k0 + i) * N + n0 + tx];
    __syncthreads();
    for (int i = ty; i < 32; i += 8)
        Wt[(size_t)(n0 + i) * K + k0 + tx] = tile[tx][i];
}

// ---------------- preprocessing #2: fused scan + dinv (+ re-zero degi) -----
__global__ void __launch_bounds__(1024) k_scan_all(
    int* __restrict__ deg, float* __restrict__ dinv,
    int* __restrict__ rowptr, int* __restrict__ cursor, int n, int e) {
    __shared__ int sh[1024];
    int t = threadIdx.x;
    int per = (n + 1023) >> 10;
    int lo = t * per, hi = min(lo + per, n);
    int sum = 0;
    for (int i = lo; i < hi; i++) sum += deg[i];
    sh[t] = sum;
    __syncthreads();
    for (int o = 1; o < 1024; o <<= 1) {
        int u = (t >= o) ? sh[t - o] : 0;
        __syncthreads();
        sh[t] += u;
        __syncthreads();
    }
    int off = sh[t] - sum;
    for (int i = lo; i < hi; i++) {
        int d = deg[i];
        deg[i] = 0;                    // restore zeros for next graph replay
        rowptr[i] = off;
        cursor[i] = off;
        dinv[i] = rsqrtf((float)d + 1.0f);
        off += d;
    }
    if (t == 0) rowptr[n] = e;
}

// ---------------- preprocessing #3: bucket edges by dst --------------------
__global__ void k_bucket(const int* __restrict__ src, const int* __restrict__ dst,
                         const float* __restrict__ dinv, int* __restrict__ cursor,
                         int* __restrict__ esrc, float* __restrict__ enorm, int e) {
    int i = blockIdx.x * blockDim.x + threadIdx.x;
    if (i < e) {
        int s = src[i], d = dst[i];
        int pos = atomicAdd(&cursor[d], 1);
        esrc[pos] = s;
        enorm[pos] = dinv[s] * dinv[d];
    }
}

// ---------------- BIG TF32 GEMM: 128x128 tile, 3-stage, ldmatrix -----------
// C[M,N] = A[M,K] @ Bt^T, Bt is [N][K] k-contiguous. N%128==0, K%32==0.
// 8 warps: 4 in M x 2 in N, warp tile 32x64. 2 CTAs/SM (reg + smem capped).
// MODE: 0 raw, 1 +bias+addmat, 2 gelu(x+bias)
#define BPITCH 36
#define BIG_STAGES 3
#define BIG_A_STAGE (128 * BPITCH)
#define BIG_B_STAGE (128 * BPITCH)
#define BIG_STAGE   (BIG_A_STAGE + BIG_B_STAGE)
#define BIG_SMEM_BYTES (BIG_STAGES * BIG_STAGE * 4)   // 110592

template <int MODE>
__global__ void __launch_bounds__(256, 2) sgemm_big(
    const float* __restrict__ A, const float* __restrict__ Bt, float* __restrict__ C,
    int M, int K, int N, const float* __restrict__ bias, const float* __restrict__ add) {
    extern __shared__ float smem[];
    const uint32_t smem_u32 = (uint32_t)__cvta_generic_to_shared(smem);

    const int tid  = threadIdx.x;
    const int lane = tid & 31;
    const int wid  = tid >> 5;
    const int wm = wid & 3, wn = wid >> 2;
    const int gid = lane >> 2, tig = lane & 3;
    const int row0 = blockIdx.y * 128;
    const int col0 = blockIdx.x * 128;

    const int lr[4] = {(tid + 0) >> 3, (tid + 256) >> 3, (tid + 512) >> 3, (tid + 768) >> 3};
    const int lk = (tid & 7) * 4;

    const int k_tiles = K >> 5;

    auto load_stage = [&](int s, int k0) {
        float* as = smem + s * BIG_STAGE;
        float* bs = as + BIG_A_STAGE;
        #pragma unroll
        for (int i = 0; i < 4; i++) {
            int row = lr[i];
            int grow = row0 + row;
            int ok = (grow < M) ? 16 : 0;
            if (!ok) grow = M - 1;
            cp16(&as[row * BPITCH + lk], &A[(size_t)grow * K + k0 + lk], ok);
        }
        #pragma unroll
        for (int i = 0; i < 4; i++) {
            int n = lr[i];
            cp16(&bs[n * BPITCH + lk], &Bt[(size_t)(col0 + n) * K + k0 + lk], 16);
        }
    };

    const int a_i = lane & 7, a_t = lane >> 3;
    const uint32_t a_off = ((uint32_t)((wm * 32 + a_i + ((a_t & 1) << 3)) * BPITCH
                                       + ((a_t >> 1) << 2))) * 4u;
    const int b_i = lane & 7, b_t = (lane >> 3) & 1;
    const uint32_t b_off = ((uint32_t)((wn * 64 + b_i) * BPITCH + (b_t << 2))) * 4u;

    float acc[2][8][4];
    #pragma unroll
    for (int i = 0; i < 2; i++)
        #pragma unroll
        for (int j = 0; j < 8; j++)
            #pragma unroll
            for (int k = 0; k < 4; k++) acc[i][j][k] = 0.0f;

    // prologue: prefetch 2 stages
    #pragma unroll
    for (int s = 0; s < BIG_STAGES - 1; s++) {
        if (s < k_tiles) load_stage(s, s * 32);
        cp_commit();
    }

    for (int t = 0; t < k_tiles; t++) {
        cp_wait<BIG_STAGES - 2>();      // keep 1 group (next tile) in flight
        __syncthreads();
        const int st = t % BIG_STAGES;

        // issue the t+2 load into the buffer just released by iteration t-1
        int nt2 = t + BIG_STAGES - 1;
        if (nt2 < k_tiles) load_stage(nt2 % BIG_STAGES, nt2 * 32);
        cp_commit();

        const uint32_t as_base = smem_u32 + (uint32_t)(st * BIG_STAGE) * 4u;
        const uint32_t bs_base = as_base + (uint32_t)BIG_A_STAGE * 4u;

        #pragma unroll
        for (int kb = 0; kb < 32; kb += 8) {
            uint32_t af[2][4], bf[8][2];
            #pragma unroll
            for (int mt = 0; mt < 2; mt++)
                ldsm_x4(af[mt], as_base + a_off + (uint32_t)(mt * 16 * BPITCH + kb) * 4u);
            #pragma unroll
            for (int nt = 0; nt < 8; nt++)
                ldsm_x2(bf[nt], bs_base + b_off + (uint32_t)(nt * 8 * BPITCH + kb) * 4u);
            #pragma unroll
            for (int mt = 0; mt < 2; mt++)
                #pragma unroll
                for (int nt = 0; nt < 8; nt++)
                    mma_tf32(acc[mt][nt], af[mt], bf[nt]);
        }
    }

    #pragma unroll
    for (int mt = 0; mt < 2; mt++) {
        #pragma unroll
        for (int half = 0; half < 2; half++) {
            int row = row0 + wm * 32 + mt * 16 + gid + half * 8;
            if (row >= M) continue;
            #pragma unroll
            for (int nt = 0; nt < 8; nt++) {
                int col = col0 + wn * 64 + nt * 8 + tig * 2;
                float v0 = acc[mt][nt][half * 2 + 0];
                float v1 = acc[mt][nt][half * 2 + 1];
                size_t o = (size_t)row * N + col;
                if (MODE == 1) {
                    v0 += bias[col]     + add[o];
                    v1 += bias[col + 1] + add[o + 1];
                } else if (MODE == 2) {
                    v0 = gelu_exact(v0 + bias[col]);
                    v1 = gelu_exact(v1 + bias[col + 1]);
                }
                *(float2*)&C[o] = make_float2(v0, v1);
            }
        }
    }
}

// ---------------- SMALL TF32 GEMM (N=64 logits), 3-stage, ldmatrix ---------
#define S_STAGES 3
#define S_A_STAGE (128 * BPITCH)
#define S_B_STAGE (64 * BPITCH)
#define S_SMEM_BYTES (S_STAGES * (S_A_STAGE + S_B_STAGE) * 4)   // 82944

__global__ void __launch_bounds__(256) sgemm_small(
    const float* __restrict__ A, const float* __restrict__ Bt, float* __restrict__ C,
    int M, int K, int N) {
    extern __shared__ float smem[];
    const uint32_t smem_u32 = (uint32_t)__cvta_generic_to_shared(smem);

    const int tid  = threadIdx.x;
    const int lane = tid & 31;
    const int wid  = tid >> 5;
    const int wm = wid & 3, wn = wid >> 2;
    const int gid = lane >> 2, tig = lane & 3;
    const int row0 = blockIdx.y * 128;
    const int col0 = 0;

    const int ar[4] = {(tid + 0) >> 3, (tid + 256) >> 3, (tid + 512) >> 3, (tid + 768) >> 3};
    const int ak = (tid & 7) * 4;
    const int bn[2] = {(tid + 0) >> 3, (tid + 256) >> 3};
    const int bk = (tid & 7) * 4;

    const int k_tiles = K >> 5;

    auto load_stage = [&](int s, int k0) {
        float* as = smem + s * S_A_STAGE;
        float* bs = smem + S_STAGES * S_A_STAGE + s * S_B_STAGE;
        #pragma unroll
        for (int i = 0; i < 4; i++) {
            int row = ar[i];
            int grow = row0 + row;
            int ok = (grow < M) ? 16 : 0;
            if (!ok) grow = M - 1;
            cp16(&as[row * BPITCH + ak], &A[(size_t)grow * K + k0 + ak], ok);
        }
        #pragma unroll
        for (int i = 0; i < 2; i++) {
            int n = bn[i];
            cp16(&bs[n * BPITCH + bk], &Bt[(size_t)(col0 + n) * K + k0 + bk], 16);
        }
    };

    const int a_i = lane & 7, a_t = lane >> 3;
    const uint32_t a_off = ((uint32_t)((wm * 32 + a_i + ((a_t & 1) << 3)) * BPITCH
                                       + ((a_t >> 1) << 2))) * 4u;
    const int b_i = lane & 7, b_t = (lane >> 3) & 1;
    const uint32_t b_off = ((uint32_t)((wn * 32 + b_i) * BPITCH + (b_t << 2))) * 4u;

    float acc[2][4][4];
    #pragma unroll
    for (int i = 0; i < 2; i++)
        #pragma unroll
        for (int j = 0; j < 4; j++)
            #pragma unroll
            for (int k = 0; k < 4; k++) acc[i][j][k] = 0.0f;

    #pragma unroll
    for (int s = 0; s < S_STAGES - 1; s++) {
        if (s < k_tiles) load_stage(s, s * 32);
        cp_commit();
    }

    for (int t = 0; t < k_tiles; t++) {
        cp_wait<S_STAGES - 2>();
        __syncthreads();
        const int st = t % S_STAGES;

        int nt2 = t + S_STAGES - 1;
        if (nt2 < k_tiles) load_stage(nt2 % S_STAGES, nt2 * 32);
        cp_commit();

        const uint32_t as_base = smem_u32 + (uint32_t)(st * S_A_STAGE) * 4u;
        const uint32_t bs_base = smem_u32 + (uint32_t)(S_STAGES * S_A_STAGE + st * S_B_STAGE) * 4u;

        #pragma unroll
        for (int kb = 0; kb < 32; kb += 8) {
            uint32_t af[2][4], bf[4][2];
            #pragma unroll
            for (int mt = 0; mt < 2; mt++)
                ldsm_x4(af[mt], as_base + a_off + (uint32_t)(mt * 16 * BPITCH + kb) * 4u);
            #pragma unroll
            for (int nt = 0; nt < 4; nt++)
                ldsm_x2(bf[nt], bs_base + b_off + (uint32_t)(nt * 8 * BPITCH + kb) * 4u);
            #pragma unroll
            for (int mt = 0; mt < 2; mt++)
                #pragma unroll
                for (int nt = 0; nt < 4; nt++)
                    mma_tf32(acc[mt][nt], af[mt], bf[nt]);
        }
    }

    #pragma unroll
    for (int mt = 0; mt < 2; mt++) {
        #pragma unroll
        for (int half = 0; half < 2; half++) {
            int row = row0 + wm * 32 + mt * 16 + gid + half * 8;
            if (row >= M) continue;
            #pragma unroll
            for (int nt = 0; nt < 4; nt++) {
                int col = col0 + wn * 32 + nt * 8 + tig * 2;
                size_t o = (size_t)row * N + col;
                *(float2*)&C[o] = make_float2(acc[mt][nt][half * 2 + 0],
                                              acc[mt][nt][half * 2 + 1]);
            }
        }
    }
}

// ---------------- fused gather + conv-epilogue + LN + GELU (float4) --------
__global__ void __launch_bounds__(256) gcn_post(
    const float* __restrict__ hw, const float* __restrict__ pp,
    const int* __restrict__ rowptr, const int* __restrict__ esrc,
    const float* __restrict__ enorm, const float* __restrict__ dinv,
    const float* __restrict__ bcv, const float* __restrict__ bpv,
    const float* __restrict__ gv, const float* __restrict__ bev,
    float* __restrict__ skip_out, float* __restrict__ h_out) {
    int r = blockIdx.x;
    int tid = threadIdx.x;
    int g = tid & 63;
    int e = tid >> 6;
    int lane = tid & 31;
    int warp = tid >> 5;
    int beg = rowptr[r], end = rowptr[r + 1];

    float4 acc = make_float4(0.f, 0.f, 0.f, 0.f);
    for (int j = beg + e; j < end; j += 4) {
        int s = __ldg(&esrc[j]);
        float w = __ldg(&enorm[j]);
        const float4 v = *(const float4*)&hw[(size_t)s * 256 + g * 4];
        acc.x = fmaf(v.x, w, acc.x);
        acc.y = fmaf(v.y, w, acc.y);
        acc.z = fmaf(v.z, w, acc.z);
        acc.w = fmaf(v.w, w, acc.w);
    }
    __shared__ float4 sacc[256];
    sacc[tid] = acc;
    __syncthreads();

    float4 t = make_float4(0.f, 0.f, 0.f, 0.f);
    float partial = 0.f;
    size_t base = (size_t)r * 256 + g * 4;
    if (tid < 64) {
        float4 a0 = sacc[g], a1 = sacc[g + 64], a2 = sacc[g + 128], a3 = sacc[g + 192];
        float ax = a0.x + a1.x + a2.x + a3.x;
        float ay = a0.y + a1.y + a2.y + a3.y;
        float az = a0.z + a1.z + a2.z + a3.z;
        float aw = a0.w + a1.w + a2.w + a3.w;
        float di = dinv[r];
        float d2 = di * di;
        float4 hv = *(const float4*)&hw[base];
        float4 pv = *(const float4*)&pp[base];
        float4 bc4 = *(const float4*)&bcv[g * 4];
        float4 bp4 = *(const float4*)&bpv[g * 4];
        t.x = ax + d2 * hv.x + bc4.x + pv.x + bp4.x;
        t.y = ay + d2 * hv.y + bc4.y + pv.y + bp4.y;
        t.z = az + d2 * hv.z + bc4.z + pv.z + bp4.z;
        t.w = aw + d2 * hv.w + bc4.w + pv.w + bp4.w;
        *(float4*)&skip_out[base] = t;
        partial = t.x + t.y + t.z + t.w;
    }

    __shared__ float red[8];
    float s = partial;
    #pragma unroll
    for (int o = 16; o > 0; o >>= 1) s += __shfl_xor_sync(0xffffffffu, s, o);
    if (lane == 0) red[warp] = s;
    __syncthreads();
    float m = 0.f;
    #pragma unroll
    for (int i = 0; i < 8; i++) m += red[i];
    m *= (1.0f / 256.0f);
    __syncthreads();

    float vpart = 0.f;
    float dx = 0.f, dy = 0.f, dz = 0.f, dw = 0.f;
    if (tid < 64) {
        dx = t.x - m; dy = t.y - m; dz = t.z - m; dw = t.w - m;
        vpart = dx * dx + dy * dy + dz * dz + dw * dw;
    }
    float sv = vpart;
    #pragma unroll
    for (int o = 16; o > 0; o >>= 1) sv += __shfl_xor_sync(0xffffffffu, sv, o);
    if (lane == 0) red[warp] = sv;
    __syncthreads();
    float var = 0.f;
    #pragma unroll
    for (int i = 0; i < 8; i++) var += red[i];
    var *= (1.0f / 256.0f);

    if (tid < 64) {
        float rs = rsqrtf(var + 1e-5f);
        float4 g4 = *(const float4*)&gv[g * 4];
        float4 b4 = *(const float4*)&bev[g * 4];
        float4 y;
        y.x = gelu_exact(dx * rs * g4.x + b4.x);
        y.y = gelu_exact(dy * rs * g4.y + b4.y);
        y.z = gelu_exact(dz * rs * g4.z + b4.z);
        y.w = gelu_exact(dw * rs * g4.w + b4.w);
        *(float4*)&h_out[base] = y;
    }
}

// ---------------- log-softmax over 64 logits -------------------------------
__global__ void k_logsoftmax(const float* __restrict__ logits, const float* __restrict__ bf2,
                             float* __restrict__ out, int Nn) {
    int r = blockIdx.x * 8 + (threadIdx.x >> 5);
    int lane = threadIdx.x & 31;
    if (r >= Nn) return;
    float v0 = logits[(size_t)r * 64 + lane]      + bf2[lane];
    float v1 = logits[(size_t)r * 64 + 32 + lane] + bf2[32 + lane];
    float mx = fmaxf(v0, v1);
    #pragma unroll
    for (int o = 16; o > 0; o >>= 1) mx = fmaxf(mx, __shfl_xor_sync(0xffffffffu, mx, o));
    float s = expf(v0 - mx) + expf(v1 - mx);
    #pragma unroll
    for (int o = 16; o > 0; o >>= 1) s += __shfl_xor_sync(0xffffffffu, s, o);
    float ls = logf(s);
    out[(size_t)r * 64 + lane]      = v0 - mx - ls;
    out[(size_t)r * 64 + 32 + lane] = v1 - mx - ls;
}

// ---------------- launch ---------------------------------------------------
extern "C" void kernel_launch(void* const* d_in, const int* in_sizes, int n_in,
                              void* d_out, int out_size) {
    const float* x  = (const float*)d_in[0];
    const int*   ei = (const int*)d_in[1];
    int E  = in_sizes[1] / 2;
    int Nn = in_sizes[0] / 128;
    const int* src = ei;
    const int* dst = ei + E;

    const float* Wc[3] = {(const float*)d_in[2],  (const float*)d_in[8],  (const float*)d_in[14]};
    const float* bc[3] = {(const float*)d_in[3],  (const float*)d_in[9],  (const float*)d_in[15]};
    const float* Wp[3] = {(const float*)d_in[4],  (const float*)d_in[10], (const float*)d_in[16]};
    const float* bp[3] = {(const float*)d_in[5],  (const float*)d_in[11], (const float*)d_in[17]};
    const float* gg[3] = {(const float*)d_in[6],  (const float*)d_in[12], (const float*)d_in[18]};
    const float* be[3] = {(const float*)d_in[7],  (const float*)d_in[13], (const float*)d_in[19]};
    const float* W_in = (const float*)d_in[20];
    const float* b_in = (const float*)d_in[21];
    const float* Wf1  = (const float*)d_in[22];
    const float* bf1  = (const float*)d_in[23];
    const float* Wf2  = (const float*)d_in[24];
    const float* bf2  = (const float*)d_in[25];
    float* out = (float*)d_out;

    cudaFuncSetAttribute(sgemm_big<0>, cudaFuncAttributeMaxDynamicSharedMemorySize, BIG_SMEM_BYTES);
    cudaFuncSetAttribute(sgemm_big<1>, cudaFuncAttributeMaxDynamicSharedMemorySize, BIG_SMEM_BYTES);
    cudaFuncSetAttribute(sgemm_big<2>, cudaFuncAttributeMaxDynamicSharedMemorySize, BIG_SMEM_BYTES);
    cudaFuncSetAttribute(sgemm_small,  cudaFuncAttributeMaxDynamicSharedMemorySize, S_SMEM_BYTES);

    float *pH, *pSkip, *pHw, *pP, *pF1, *pLog, *pDinv, *pEn, *pWt;
    int *pDegi, *pRp, *pCur, *pEs;
    cudaGetSymbolAddress((void**)&pH,    g_h);
    cudaGetSymbolAddress((void**)&pSkip, g_skip);
    cudaGetSymbolAddress((void**)&pHw,   g_hw);
    cudaGetSymbolAddress((void**)&pP,    g_p);
    cudaGetSymbolAddress((void**)&pF1,   g_f1);
    cudaGetSymbolAddress((void**)&pLog,  g_logits);
    cudaGetSymbolAddress((void**)&pDinv, g_dinv);
    cudaGetSymbolAddress((void**)&pDegi, g_degi);
    cudaGetSymbolAddress((void**)&pRp,   g_rowptr);
    cudaGetSymbolAddress((void**)&pCur,  g_cursor);
    cudaGetSymbolAddress((void**)&pEs,   g_esrc);
    cudaGetSymbolAddress((void**)&pEn,   g_enorm);
    cudaGetSymbolAddress((void**)&pWt,   g_wt);

    // Transposed-weight offsets (floats):
    //   [0] Wc0  [32768] Wp0  [65536] Wc1  [131072] Wp1
    //   [196608] Wc2  [262144] Wp2  [327680] W_in  [360448] Wf1  [491520] Wf2
    TransArgs ta;
    const float* Ws[9] = {Wc[0], Wp[0], Wc[1], Wp[1], Wc[2], Wp[2], W_in, Wf1, Wf2};
    int Ks[9]  = {128, 128, 256, 256, 256, 256, 128, 256, 512};
    int Nss[9] = {256, 256, 256, 256, 256, 256, 256, 512, 64};
    long long woff[9] = {0, 32768, 65536, 131072, 196608, 262144, 327680, 360448, 491520};
    int total_tiles = 0;
    for (int i = 0; i < 9; i++) {
        ta.W[i] = Ws[i];
        ta.K[i] = Ks[i];
        ta.N[i] = Nss[i];
        ta.woff[i] = woff[i];
        ta.tiles[i] = (Ks[i] >> 5) * (Nss[i] >> 5);
        total_tiles += ta.tiles[i];
    }

    // --- preprocessing: 3 kernels, so the first GEMM is launch #4 (profiled) ---
    int cblocks = (E + 255) / 256;
    k_count_transpose<<<cblocks + total_tiles, 256>>>(ta, pWt, pDegi, dst, E, cblocks);
    k_scan_all<<<1, 1024>>>(pDegi, pDinv, pRp, pCur, Nn, E);
    k_bucket<<<(E + 255) / 256, 256>>>(src, dst, pDinv, pCur, pEs, pEn, E);

    int gy = (Nn + 127) / 128;

    // --- 3 GCN layers (layer 0: h == skip == x) ---
    const float* h    = x;
    const float* skip = x;
    int Kin = 128;
    for (int l = 0; l < 3; l++) {
        sgemm_big<0><<<dim3(2, gy), 256, BIG_SMEM_BYTES>>>(h,    pWt + woff[2 * l],     pHw, Nn, Kin, 256, nullptr, nullptr);
        sgemm_big<0><<<dim3(2, gy), 256, BIG_SMEM_BYTES>>>(skip, pWt + woff[2 * l + 1], pP,  Nn, Kin, 256, nullptr, nullptr);
        gcn_post<<<Nn, 256>>>(pHw, pP, pRp, pEs, pEn, pDinv,
                              bc[l], bp[l], gg[l], be[l], pSkip, pH);
        h = pH; skip = pSkip; Kin = 256;
    }

    // --- long residual (fused epilogue) + MLP head ---
    sgemm_big<1><<<dim3(2, gy), 256, BIG_SMEM_BYTES>>>(x, pWt + woff[6], pHw, Nn, 128, 256, b_in, pH);
    sgemm_big<2><<<dim3(4, gy), 256, BIG_SMEM_BYTES>>>(pHw, pWt + woff[7], pF1, Nn, 256, 512, bf1, nullptr);
    sgemm_small<<<dim3(1, gy), 256, S_SMEM_BYTES>>>(pF1, pWt + woff[8], pLog, Nn, 512, 64);
    k_logsoftmax<<<(Nn + 7) / 8, 256>>>(pLog, bf2, out, Nn);
}

// round 15
// speedup vs baseline: 1.1202x; 1.1124x over previous
#include <cuda_runtime.h>
#include <cuda_fp16.h>
#include <math.h>
#include <stdint.h>

#define MAXN 50048
#define MAXE 800000

// ---------------- scratch (device globals; no allocation allowed) ----------
__device__ __align__(128) float  g_h[MAXN * 256];       // fp32 h (MODE1 add input)
__device__ __align__(128) float  g_hw[MAXN * 256];      // conv GEMM out (fp32)
__device__ __align__(128) float  g_p[MAXN * 256];       // skip GEMM out (fp32)
__device__ __align__(128) float  g_logits[MAXN * 64];
__device__ __align__(128) __half g_xh[MAXN * 128];      // half x
__device__ __align__(128) __half g_hH[MAXN * 256];      // half h
__device__ __align__(128) __half g_skipH[MAXN * 256];   // half skip
__device__ __align__(128) __half g_hwH[MAXN * 256];     // half (x@W_in + b + h)
__device__ __align__(128) __half g_f1H[MAXN * 512];     // half gelu(f1)
__device__ __align__(128) __half g_wtH[524288];         // transposed half weights
__device__ __align__(128) float  g_dinv[MAXN];
__device__ __align__(128) int    g_degi[MAXN];          // zero-init; re-zeroed each run
__device__ __align__(128) int    g_rowptr[MAXN + 1];
__device__ __align__(128) int    g_cursor[MAXN];
__device__ __align__(128) int    g_esrc[MAXE];
__device__ __align__(128) float  g_enorm[MAXE];

// ---------------- helpers --------------------------------------------------
__device__ __forceinline__ float gelu_exact(float x) {
    return 0.5f * x * (1.0f + erff(x * 0.70710678118654752440f));
}
__device__ __forceinline__ void mma_f16(float* c, const uint32_t* a, const uint32_t* b) {
    asm("mma.sync.aligned.m16n8k16.row.col.f32.f16.f16.f32 "
        "{%0,%1,%2,%3},{%4,%5,%6,%7},{%8,%9},{%0,%1,%2,%3};"
        : "+f"(c[0]), "+f"(c[1]), "+f"(c[2]), "+f"(c[3])
        : "r"(a[0]), "r"(a[1]), "r"(a[2]), "r"(a[3]), "r"(b[0]), "r"(b[1]));
}
__device__ __forceinline__ void ldsm_x4(uint32_t* r, uint32_t saddr) {
    asm volatile("ldmatrix.sync.aligned.m8n8.x4.shared.b16 {%0,%1,%2,%3}, [%4];"
                 : "=r"(r[0]), "=r"(r[1]), "=r"(r[2]), "=r"(r[3]) : "r"(saddr));
}
__device__ __forceinline__ void ldsm_x2(uint32_t* r, uint32_t saddr) {
    asm volatile("ldmatrix.sync.aligned.m8n8.x2.shared.b16 {%0,%1}, [%2];"
                 : "=r"(r[0]), "=r"(r[1]) : "r"(saddr));
}
__device__ __forceinline__ void cp16(void* dst, const void* src, int bytes) {
    uint32_t d = (uint32_t)__cvta_generic_to_shared(dst);
    asm volatile("cp.async.cg.shared.global [%0], [%1], 16, %2;"
                 :: "r"(d), "l"(src), "r"(bytes));
}
__device__ __forceinline__ void cp_commit() { asm volatile("cp.async.commit_group;"); }
template <int N>
__device__ __forceinline__ void cp_wait() { asm volatile("cp.async.wait_group %0;" :: "n"(N)); }

// ---------------- preprocessing #1: count + transpose(fp32->half) + x->half
struct TransArgs {
    const float* W[9];
    long long    woff[9];
    int K[9];
    int N[9];
    int tiles[9];
};
__global__ void k_count_transpose(TransArgs a, __half* wt, __half* xh, const float* x,
                                  int* degi, const int* __restrict__ dst,
                                  int e, int cblocks, int tblocks, int xcount) {
    int b = blockIdx.x;
    if (b < cblocks) {                       // degree count
        int i = b * 256 + threadIdx.x;
        if (i < e) atomicAdd(&degi[dst[i]], 1);
        return;
    }
    b -= cblocks;
    if (b >= tblocks) {                      // x -> half
        int i = (b - tblocks) * 256 + threadIdx.x;
        if (i < xcount) xh[i] = __float2half_rn(x[i]);
        return;
    }
    __shared__ float tile[32][33];
    int t = b;
    int m = 0;
    while (t >= a.tiles[m]) { t -= a.tiles[m]; m++; }
    int K = a.K[m], N = a.N[m];
    int ntx = N >> 5;
    int k0 = (t / ntx) * 32, n0 = (t % ntx) * 32;
    const float* W = a.W[m];
    __half* Wt = wt + a.woff[m];
    int tx = threadIdx.x & 31, ty = threadIdx.x >> 5;   // 32 x 8
    for (int i = ty; i < 32; i += 8)
        tile[i][tx] = W[(size_t)(k0 + i) * N + n0 + tx];
    __syncthreads();
    for (int i = ty; i < 32; i += 8)
        Wt[(size_t)(n0 + i) * K + k0 + tx] = __float2half_rn(tile[tx][i]);
}

// ---------------- preprocessing #2: fused scan + dinv (+ re-zero degi) -----
__global__ void __launch_bounds__(1024) k_scan_all(
    int* __restrict__ deg, float* __restrict__ dinv,
    int* __restrict__ rowptr, int* __restrict__ cursor, int n, int e) {
    __shared__ int sh[1024];
    int t = threadIdx.x;
    int per = (n + 1023) >> 10;
    int lo = t * per, hi = min(lo + per, n);
    int sum = 0;
    for (int i = lo; i < hi; i++) sum += deg[i];
    sh[t] = sum;
    __syncthreads();
    for (int o = 1; o < 1024; o <<= 1) {
        int u = (t >= o) ? sh[t - o] : 0;
        __syncthreads();
        sh[t] += u;
        __syncthreads();
    }
    int off = sh[t] - sum;
    for (int i = lo; i < hi; i++) {
        int d = deg[i];
        deg[i] = 0;
        rowptr[i] = off;
        cursor[i] = off;
        dinv[i] = rsqrtf((float)d + 1.0f);
        off += d;
    }
    if (t == 0) rowptr[n] = e;
}

// ---------------- preprocessing #3: bucket edges by dst --------------------
__global__ void k_bucket(const int* __restrict__ src, const int* __restrict__ dst,
                         const float* __restrict__ dinv, int* __restrict__ cursor,
                         int* __restrict__ esrc, float* __restrict__ enorm, int e) {
    int i = blockIdx.x * blockDim.x + threadIdx.x;
    if (i < e) {
        int s = src[i], d = dst[i];
        int pos = atomicAdd(&cursor[d], 1);
        esrc[pos] = s;
        enorm[pos] = dinv[s] * dinv[d];
    }
}

// ---------------- FP16 tensor-core GEMM: 128x128 tile, 2-stage -------------
// C[M,N] = A[M,K] @ Bt^T; A half [M][K], Bt half [N][K]. K%32==0, N%128==0.
// 8 warps (4 M x 2 N), warp tile 32x64, m16n8k16. 2 CTAs/SM.
// MODE 0: fp32 C.  MODE 1: half Ch = C + bias + add(fp32).  MODE 2: half Ch = gelu(C+bias).
#define HPITCH 40                              // halves per row (32 data + 8 pad)
#define H_A_STAGE (128 * HPITCH)               // halves
#define H_B_STAGE (128 * HPITCH)
#define H_STAGE   (H_A_STAGE + H_B_STAGE)
#define H_SMEM_BYTES (2 * H_STAGE * 2)         // 40960

template <int MODE>
__global__ void __launch_bounds__(256, 2) gemm_h(
    const __half* __restrict__ A, const __half* __restrict__ Bt,
    float* __restrict__ C, __half* __restrict__ Ch,
    int M, int K, int N, const float* __restrict__ bias, const float* __restrict__ add) {
    extern __shared__ __half smh[];
    const uint32_t smem_u32 = (uint32_t)__cvta_generic_to_shared(smh);

    const int tid  = threadIdx.x;
    const int lane = tid & 31;
    const int wid  = tid >> 5;
    const int wm = wid & 3, wn = wid >> 2;
    const int gid = lane >> 2, tig = lane & 3;
    const int row0 = blockIdx.y * 128;
    const int col0 = blockIdx.x * 128;

    // loaders: A/B stage = 128 rows x 4 chunks(16B) = 512 chunks; 2 per thread
    const int lr[2] = {(tid + 0) >> 2, (tid + 256) >> 2};
    const int lc = (tid & 3) * 8;              // half offset within row

    const int k_tiles = K >> 5;

    auto load_stage = [&](int s, int k0) {
        __half* as = smh + s * H_STAGE;
        __half* bs = as + H_A_STAGE;
        #pragma unroll
        for (int i = 0; i < 2; i++) {
            int row = lr[i];
            int grow = row0 + row;
            int ok = (grow < M) ? 16 : 0;
            if (!ok) grow = M - 1;
            cp16(&as[row * HPITCH + lc], &A[(size_t)grow * K + k0 + lc], ok);
        }
        #pragma unroll
        for (int i = 0; i < 2; i++) {
            int n = lr[i];
            cp16(&bs[n * HPITCH + lc], &Bt[(size_t)(col0 + n) * K + k0 + lc], 16);
        }
    };

    // ldmatrix lane offsets (bytes)
    const uint32_t a_off = ((uint32_t)((wm * 32 + (lane & 15)) * HPITCH + (lane >> 4) * 8)) * 2u;
    const uint32_t b_off = ((uint32_t)((wn * 64 + (lane & 7)) * HPITCH + ((lane >> 3) & 1) * 8)) * 2u;

    float acc[2][8][4];
    #pragma unroll
    for (int i = 0; i < 2; i++)
        #pragma unroll
        for (int j = 0; j < 8; j++)
            #pragma unroll
            for (int k = 0; k < 4; k++) acc[i][j][k] = 0.0f;

    load_stage(0, 0);
    cp_commit();

    for (int t = 0; t < k_tiles; t++) {
        cp_wait<0>();
        __syncthreads();
        const int st = t & 1;
        if (t + 1 < k_tiles) load_stage((t + 1) & 1, (t + 1) * 32);
        cp_commit();

        const uint32_t as_base = smem_u32 + (uint32_t)(st * H_STAGE) * 2u;
        const uint32_t bs_base = as_base + (uint32_t)H_A_STAGE * 2u;

        #pragma unroll
        for (int ks = 0; ks < 2; ks++) {       // two K=16 steps per BK=32 tile
            uint32_t af[2][4], bf[8][2];
            #pragma unroll
            for (int mt = 0; mt < 2; mt++)
                ldsm_x4(af[mt], as_base + a_off + (uint32_t)(mt * 16 * HPITCH + ks * 16) * 2u);
            #pragma unroll
            for (int nt = 0; nt < 8; nt++)
                ldsm_x2(bf[nt], bs_base + b_off + (uint32_t)(nt * 8 * HPITCH + ks * 16) * 2u);
            #pragma unroll
            for (int mt = 0; mt < 2; mt++)
                #pragma unroll
                for (int nt = 0; nt < 8; nt++)
                    mma_f16(acc[mt][nt], af[mt], bf[nt]);
        }
    }

    #pragma unroll
    for (int mt = 0; mt < 2; mt++) {
        #pragma unroll
        for (int half_ = 0; half_ < 2; half_++) {
            int row = row0 + wm * 32 + mt * 16 + gid + half_ * 8;
            if (row >= M) continue;
            #pragma unroll
            for (int nt = 0; nt < 8; nt++) {
                int col = col0 + wn * 64 + nt * 8 + tig * 2;
                float v0 = acc[mt][nt][half_ * 2 + 0];
                float v1 = acc[mt][nt][half_ * 2 + 1];
                size_t o = (size_t)row * N + col;
                if (MODE == 0) {
                    *(float2*)&C[o] = make_float2(v0, v1);
                } else if (MODE == 1) {
                    v0 += bias[col]     + add[o];
                    v1 += bias[col + 1] + add[o + 1];
                    *(__half2*)&Ch[o] = __floats2half2_rn(v0, v1);
                } else {
                    v0 = gelu_exact(v0 + bias[col]);
                    v1 = gelu_exact(v1 + bias[col + 1]);
                    *(__half2*)&Ch[o] = __floats2half2_rn(v0, v1);
                }
            }
        }
    }
}

// ---------------- FP16 small GEMM (N=64 logits), 2-stage -------------------
#define HS_A_STAGE (128 * HPITCH)
#define HS_B_STAGE (64 * HPITCH)
#define HS_STAGE   (HS_A_STAGE + HS_B_STAGE)
#define HS_SMEM_BYTES (2 * HS_STAGE * 2)       // 30720

__global__ void __launch_bounds__(256) gemm_small_h(
    const __half* __restrict__ A, const __half* __restrict__ Bt, float* __restrict__ C,
    int M, int K, int N) {
    extern __shared__ __half smh[];
    const uint32_t smem_u32 = (uint32_t)__cvta_generic_to_shared(smh);

    const int tid  = threadIdx.x;
    const int lane = tid & 31;
    const int wid  = tid >> 5;
    const int wm = wid & 3, wn = wid >> 2;
    const int gid = lane >> 2, tig = lane & 3;
    const int row0 = blockIdx.y * 128;

    const int lr[2] = {(tid + 0) >> 2, (tid + 256) >> 2};
    const int lc = (tid & 3) * 8;
    const int bn = tid >> 2;                   // 256 B-chunks: 1 per thread (tid<256)
    const int k_tiles = K >> 5;

    auto load_stage = [&](int s, int k0) {
        __half* as = smh + s * HS_STAGE;
        __half* bs = as + HS_A_STAGE;
        #pragma unroll
        for (int i = 0; i < 2; i++) {
            int row = lr[i];
            int grow = row0 + row;
            int ok = (grow < M) ? 16 : 0;
            if (!ok) grow = M - 1;
            cp16(&as[row * HPITCH + lc], &A[(size_t)grow * K + k0 + lc], ok);
        }
        if (bn < 64)
            cp16(&bs[bn * HPITCH + lc], &Bt[(size_t)bn * K + k0 + lc], 16);
    };

    const uint32_t a_off = ((uint32_t)((wm * 32 + (lane & 15)) * HPITCH + (lane >> 4) * 8)) * 2u;
    const uint32_t b_off = ((uint32_t)((wn * 32 + (lane & 7)) * HPITCH + ((lane >> 3) & 1) * 8)) * 2u;

    float acc[2][4][4];
    #pragma unroll
    for (int i = 0; i < 2; i++)
        #pragma unroll
        for (int j = 0; j < 4; j++)
            #pragma unroll
            for (int k = 0; k < 4; k++) acc[i][j][k] = 0.0f;

    load_stage(0, 0);
    cp_commit();

    for (int t = 0; t < k_tiles; t++) {
        cp_wait<0>();
        __syncthreads();
        const int st = t & 1;
        if (t + 1 < k_tiles) load_stage((t + 1) & 1, (t + 1) * 32);
        cp_commit();

        const uint32_t as_base = smem_u32 + (uint32_t)(st * HS_STAGE) * 2u;
        const uint32_t bs_base = as_base + (uint32_t)HS_A_STAGE * 2u;

        #pragma unroll
        for (int ks = 0; ks < 2; ks++) {
            uint32_t af[2][4], bf[4][2];
            #pragma unroll
            for (int mt = 0; mt < 2; mt++)
                ldsm_x4(af[mt], as_base + a_off + (uint32_t)(mt * 16 * HPITCH + ks * 16) * 2u);
            #pragma unroll
            for (int nt = 0; nt < 4; nt++)
                ldsm_x2(bf[nt], bs_base + b_off + (uint32_t)(nt * 8 * HPITCH + ks * 16) * 2u);
            #pragma unroll
            for (int mt = 0; mt < 2; mt++)
                #pragma unroll
                for (int nt = 0; nt < 4; nt++)
                    mma_f16(acc[mt][nt], af[mt], bf[nt]);
        }
    }

    #pragma unroll
    for (int mt = 0; mt < 2; mt++) {
        #pragma unroll
        for (int half_ = 0; half_ < 2; half_++) {
            int row = row0 + wm * 32 + mt * 16 + gid + half_ * 8;
            if (row >= M) continue;
            #pragma unroll
            for (int nt = 0; nt < 4; nt++) {
                int col = wn * 32 + nt * 8 + tig * 2;
                size_t o = (size_t)row * N + col;
                *(float2*)&C[o] = make_float2(acc[mt][nt][half_ * 2 + 0],
                                              acc[mt][nt][half_ * 2 + 1]);
            }
        }
    }
}

// ---------------- fused gather + conv-epilogue + LN + GELU -----------------
// Writes: h fp32 (for long residual), h half + skip half (GEMM feeds).
__global__ void __launch_bounds__(256) gcn_post(
    const float* __restrict__ hw, const float* __restrict__ pp,
    const int* __restrict__ rowptr, const int* __restrict__ esrc,
    const float* __restrict__ enorm, const float* __restrict__ dinv,
    const float* __restrict__ bcv, const float* __restrict__ bpv,
    const float* __restrict__ gv, const float* __restrict__ bev,
    __half* __restrict__ skipH_out, float* __restrict__ h_out,
    __half* __restrict__ hH_out) {
    int r = blockIdx.x;
    int tid = threadIdx.x;
    int g = tid & 63;
    int e = tid >> 6;
    int lane = tid & 31;
    int warp = tid >> 5;
    int beg = rowptr[r], end = rowptr[r + 1];

    float4 acc = make_float4(0.f, 0.f, 0.f, 0.f);
    for (int j = beg + e; j < end; j += 4) {
        int s = __ldg(&esrc[j]);
        float w = __ldg(&enorm[j]);
        const float4 v = *(const float4*)&hw[(size_t)s * 256 + g * 4];
        acc.x = fmaf(v.x, w, acc.x);
        acc.y = fmaf(v.y, w, acc.y);
        acc.z = fmaf(v.z, w, acc.z);
        acc.w = fmaf(v.w, w, acc.w);
    }
    __shared__ float4 sacc[256];
    sacc[tid] = acc;
    __syncthreads();

    float4 t = make_float4(0.f, 0.f, 0.f, 0.f);
    float partial = 0.f;
    size_t base = (size_t)r * 256 + g * 4;
    if (tid < 64) {
        float4 a0 = sacc[g], a1 = sacc[g + 64], a2 = sacc[g + 128], a3 = sacc[g + 192];
        float ax = a0.x + a1.x + a2.x + a3.x;
        float ay = a0.y + a1.y + a2.y + a3.y;
        float az = a0.z + a1.z + a2.z + a3.z;
        float aw = a0.w + a1.w + a2.w + a3.w;
        float di = dinv[r];
        float d2 = di * di;
        float4 hv = *(const float4*)&hw[base];
        float4 pv = *(const float4*)&pp[base];
        float4 bc4 = *(const float4*)&bcv[g * 4];
        float4 bp4 = *(const float4*)&bpv[g * 4];
        t.x = ax + d2 * hv.x + bc4.x + pv.x + bp4.x;
        t.y = ay + d2 * hv.y + bc4.y + pv.y + bp4.y;
        t.z = az + d2 * hv.z + bc4.z + pv.z + bp4.z;
        t.w = aw + d2 * hv.w + bc4.w + pv.w + bp4.w;
        __half2* sh = (__half2*)&skipH_out[base];
        sh[0] = __floats2half2_rn(t.x, t.y);
        sh[1] = __floats2half2_rn(t.z, t.w);
        partial = t.x + t.y + t.z + t.w;
    }

    __shared__ float red[8];
    float s = partial;
    #pragma unroll
    for (int o = 16; o > 0; o >>= 1) s += __shfl_xor_sync(0xffffffffu, s, o);
    if (lane == 0) red[warp] = s;
    __syncthreads();
    float m = 0.f;
    #pragma unroll
    for (int i = 0; i < 8; i++) m += red[i];
    m *= (1.0f / 256.0f);
    __syncthreads();

    float vpart = 0.f;
    float dx = 0.f, dy = 0.f, dz = 0.f, dw = 0.f;
    if (tid < 64) {
        dx = t.x - m; dy = t.y - m; dz = t.z - m; dw = t.w - m;
        vpart = dx * dx + dy * dy + dz * dz + dw * dw;
    }
    float sv = vpart;
    #pragma unroll
    for (int o = 16; o > 0; o >>= 1) sv += __shfl_xor_sync(0xffffffffu, sv, o);
    if (lane == 0) red[warp] = sv;
    __syncthreads();
    float var = 0.f;
    #pragma unroll
    for (int i = 0; i < 8; i++) var += red[i];
    var *= (1.0f / 256.0f);

    if (tid < 64) {
        float rs = rsqrtf(var + 1e-5f);
        float4 g4 = *(const float4*)&gv[g * 4];
        float4 b4 = *(const float4*)&bev[g * 4];
        float4 y;
        y.x = gelu_exact(dx * rs * g4.x + b4.x);
        y.y = gelu_exact(dy * rs * g4.y + b4.y);
        y.z = gelu_exact(dz * rs * g4.z + b4.z);
        y.w = gelu_exact(dw * rs * g4.w + b4.w);
        *(float4*)&h_out[base] = y;
        __half2* hh = (__half2*)&hH_out[base];
        hh[0] = __floats2half2_rn(y.x, y.y);
        hh[1] = __floats2half2_rn(y.z, y.w);
    }
}

// ---------------- log-softmax over 64 logits -------------------------------
__global__ void k_logsoftmax(const float* __restrict__ logits, const float* __restrict__ bf2,
                             float* __restrict__ out, int Nn) {
    int r = blockIdx.x * 8 + (threadIdx.x >> 5);
    int lane = threadIdx.x & 31;
    if (r >= Nn) return;
    float v0 = logits[(size_t)r * 64 + lane]      + bf2[lane];
    float v1 = logits[(size_t)r * 64 + 32 + lane] + bf2[32 + lane];
    float mx = fmaxf(v0, v1);
    #pragma unroll
    for (int o = 16; o > 0; o >>= 1) mx = fmaxf(mx, __shfl_xor_sync(0xffffffffu, mx, o));
    float s = expf(v0 - mx) + expf(v1 - mx);
    #pragma unroll
    for (int o = 16; o > 0; o >>= 1) s += __shfl_xor_sync(0xffffffffu, s, o);
    float ls = logf(s);
    out[(size_t)r * 64 + lane]      = v0 - mx - ls;
    out[(size_t)r * 64 + 32 + lane] = v1 - mx - ls;
}

// ---------------- launch ---------------------------------------------------
extern "C" void kernel_launch(void* const* d_in, const int* in_sizes, int n_in,
                              void* d_out, int out_size) {
    const float* x  = (const float*)d_in[0];
    const int*   ei = (const int*)d_in[1];
    int E  = in_sizes[1] / 2;
    int Nn = in_sizes[0] / 128;
    const int* src = ei;
    const int* dst = ei + E;

    const float* Wc[3] = {(const float*)d_in[2],  (const float*)d_in[8],  (const float*)d_in[14]};
    const float* bc[3] = {(const float*)d_in[3],  (const float*)d_in[9],  (const float*)d_in[15]};
    const float* Wp[3] = {(const float*)d_in[4],  (const float*)d_in[10], (const float*)d_in[16]};
    const float* bp[3] = {(const float*)d_in[5],  (const float*)d_in[11], (const float*)d_in[17]};
    const float* gg[3] = {(const float*)d_in[6],  (const float*)d_in[12], (const float*)d_in[18]};
    const float* be[3] = {(const float*)d_in[7],  (const float*)d_in[13], (const float*)d_in[19]};
    const float* W_in = (const float*)d_in[20];
    const float* b_in = (const float*)d_in[21];
    const float* Wf1  = (const float*)d_in[22];
    const float* bf1  = (const float*)d_in[23];
    const float* Wf2  = (const float*)d_in[24];
    const float* bf2  = (const float*)d_in[25];
    float* out = (float*)d_out;

    float *pH, *pHw, *pP, *pLog, *pDinv, *pEn;
    __half *pXh, *pHh, *pSkipH, *pHwH, *pF1H, *pWtH;
    int *pDegi, *pRp, *pCur, *pEs;
    cudaGetSymbolAddress((void**)&pH,    g_h);
    cudaGetSymbolAddress((void**)&pHw,   g_hw);
    cudaGetSymbolAddress((void**)&pP,    g_p);
    cudaGetSymbolAddress((void**)&pLog,  g_logits);
    cudaGetSymbolAddress((void**)&pXh,   g_xh);
    cudaGetSymbolAddress((void**)&pHh,   g_hH);
    cudaGetSymbolAddress((void**)&pSkipH,g_skipH);
    cudaGetSymbolAddress((void**)&pHwH,  g_hwH);
    cudaGetSymbolAddress((void**)&pF1H,  g_f1H);
    cudaGetSymbolAddress((void**)&pWtH,  g_wtH);
    cudaGetSymbolAddress((void**)&pDinv, g_dinv);
    cudaGetSymbolAddress((void**)&pDegi, g_degi);
    cudaGetSymbolAddress((void**)&pRp,   g_rowptr);
    cudaGetSymbolAddress((void**)&pCur,  g_cursor);
    cudaGetSymbolAddress((void**)&pEs,   g_esrc);
    cudaGetSymbolAddress((void**)&pEn,   g_enorm);

    // Transposed-half-weight offsets (halves)
    TransArgs ta;
    const float* Ws[9] = {Wc[0], Wp[0], Wc[1], Wp[1], Wc[2], Wp[2], W_in, Wf1, Wf2};
    int Ks[9]  = {128, 128, 256, 256, 256, 256, 128, 256, 512};
    int Nss[9] = {256, 256, 256, 256, 256, 256, 256, 512, 64};
    long long woff[9] = {0, 32768, 65536, 131072, 196608, 262144, 327680, 360448, 491520};
    int total_tiles = 0;
    for (int i = 0; i < 9; i++) {
        ta.W[i] = Ws[i];
        ta.K[i] = Ks[i];
        ta.N[i] = Nss[i];
        ta.woff[i] = woff[i];
        ta.tiles[i] = (Ks[i] >> 5) * (Nss[i] >> 5);
        total_tiles += ta.tiles[i];
    }

    // --- preprocessing: 3 kernels (first GEMM = launch #4, profiled) ---
    int cblocks = (E + 255) / 256;
    int xcount  = Nn * 128;
    int xblocks = (xcount + 255) / 256;
    k_count_transpose<<<cblocks + total_tiles + xblocks, 256>>>(
        ta, pWtH, pXh, x, pDegi, dst, E, cblocks, total_tiles, xcount);
    k_scan_all<<<1, 1024>>>(pDegi, pDinv, pRp, pCur, Nn, E);
    k_bucket<<<(E + 255) / 256, 256>>>(src, dst, pDinv, pCur, pEs, pEn, E);

    int gy = (Nn + 127) / 128;

    // --- 3 GCN layers (layer 0: h == skip == x) ---
    const __half* hA    = pXh;
    const __half* skipA = pXh;
    int Kin = 128;
    for (int l = 0; l < 3; l++) {
        gemm_h<0><<<dim3(2, gy), 256, H_SMEM_BYTES>>>(hA,    pWtH + woff[2 * l],     pHw, nullptr, Nn, Kin, 256, nullptr, nullptr);
        gemm_h<0><<<dim3(2, gy), 256, H_SMEM_BYTES>>>(skipA, pWtH + woff[2 * l + 1], pP,  nullptr, Nn, Kin, 256, nullptr, nullptr);
        gcn_post<<<Nn, 256>>>(pHw, pP, pRp, pEs, pEn, pDinv,
                              bc[l], bp[l], gg[l], be[l], pSkipH, pH, pHh);
        hA = pHh; skipA = pSkipH; Kin = 256;
    }

    // --- long residual (fused epilogue) + MLP head ---
    gemm_h<1><<<dim3(2, gy), 256, H_SMEM_BYTES>>>(pXh, pWtH + woff[6], nullptr, pHwH, Nn, 128, 256, b_in, pH);
    gemm_h<2><<<dim3(4, gy), 256, H_SMEM_BYTES>>>(pHwH, pWtH + woff[7], nullptr, pF1H, Nn, 256, 512, bf1, nullptr);
    gemm_small_h<<<dim3(1, gy), 256, HS_SMEM_BYTES>>>(pF1H, pWtH + woff[8], pLog, Nn, 512, 64);
    k_logsoftmax<<<(Nn + 7) / 8, 256>>>(pLog, bf2, out, Nn);
}

// round 16
// speedup vs baseline: 1.2195x; 1.0887x over previous
#include <cuda_runtime.h>
#include <cuda_fp16.h>
#include <math.h>
#include <stdint.h>

#define MAXN 50048
#define MAXE 800000

// ---------------- scratch (device globals; no allocation allowed) ----------
__device__ __align__(128) float  g_logits[MAXN * 64];
__device__ __align__(128) __half g_xh[MAXN * 128];      // half x
__device__ __align__(128) __half g_hwH[MAXN * 256];     // conv GEMM out (half)
__device__ __align__(128) __half g_pH[MAXN * 256];      // skip GEMM out (half)
__device__ __align__(128) __half g_hH[MAXN * 256];      // half h (post out)
__device__ __align__(128) __half g_skipH[MAXN * 256];   // half skip (post out)
__device__ __align__(128) __half g_resH[MAXN * 256];    // half (x@W_in + b + h)
__device__ __align__(128) __half g_f1H[MAXN * 512];     // half gelu(f1)
__device__ __align__(128) __half g_wtH[524288];         // transposed half weights
__device__ __align__(128) float  g_dinv[MAXN];
__device__ __align__(128) int    g_degi[MAXN];          // zero-init; re-zeroed each run
__device__ __align__(128) int    g_rowptr[MAXN + 1];
__device__ __align__(128) int    g_cursor[MAXN];
__device__ __align__(128) int    g_esrc[MAXE];
__device__ __align__(128) float  g_enorm[MAXE];

// ---------------- helpers --------------------------------------------------
__device__ __forceinline__ float gelu_exact(float x) {
    return 0.5f * x * (1.0f + erff(x * 0.70710678118654752440f));
}
__device__ __forceinline__ void mma_f16(float* c, const uint32_t* a, const uint32_t* b) {
    asm("mma.sync.aligned.m16n8k16.row.col.f32.f16.f16.f32 "
        "{%0,%1,%2,%3},{%4,%5,%6,%7},{%8,%9},{%0,%1,%2,%3};"
        : "+f"(c[0]), "+f"(c[1]), "+f"(c[2]), "+f"(c[3])
        : "r"(a[0]), "r"(a[1]), "r"(a[2]), "r"(a[3]), "r"(b[0]), "r"(b[1]));
}
__device__ __forceinline__ void ldsm_x4(uint32_t* r, uint32_t saddr) {
    asm volatile("ldmatrix.sync.aligned.m8n8.x4.shared.b16 {%0,%1,%2,%3}, [%4];"
                 : "=r"(r[0]), "=r"(r[1]), "=r"(r[2]), "=r"(r[3]) : "r"(saddr));
}
__device__ __forceinline__ void ldsm_x2(uint32_t* r, uint32_t saddr) {
    asm volatile("ldmatrix.sync.aligned.m8n8.x2.shared.b16 {%0,%1}, [%2];"
                 : "=r"(r[0]), "=r"(r[1]) : "r"(saddr));
}
__device__ __forceinline__ void cp16(void* dst, const void* src, int bytes) {
    uint32_t d = (uint32_t)__cvta_generic_to_shared(dst);
    asm volatile("cp.async.cg.shared.global [%0], [%1], 16, %2;"
                 :: "r"(d), "l"(src), "r"(bytes));
}
__device__ __forceinline__ void cp_commit() { asm volatile("cp.async.commit_group;"); }
template <int N>
__device__ __forceinline__ void cp_wait() { asm volatile("cp.async.wait_group %0;" :: "n"(N)); }

// ---------------- preprocessing #1: count + transpose(fp32->half) + x->half
struct TransArgs {
    const float* W[9];
    long long    woff[9];
    int K[9];
    int N[9];
    int tiles[9];
};
__global__ void k_count_transpose(TransArgs a, __half* wt, __half* xh, const float* x,
                                  int* degi, const int* __restrict__ dst,
                                  int e, int cblocks, int tblocks, int xcount) {
    int b = blockIdx.x;
    if (b < cblocks) {                       // degree count
        int i = b * 256 + threadIdx.x;
        if (i < e) atomicAdd(&degi[dst[i]], 1);
        return;
    }
    b -= cblocks;
    if (b >= tblocks) {                      // x -> half
        int i = (b - tblocks) * 256 + threadIdx.x;
        if (i < xcount) xh[i] = __float2half_rn(x[i]);
        return;
    }
    __shared__ float tile[32][33];
    int t = b;
    int m = 0;
    while (t >= a.tiles[m]) { t -= a.tiles[m]; m++; }
    int K = a.K[m], N = a.N[m];
    int ntx = N >> 5;
    int k0 = (t / ntx) * 32, n0 = (t % ntx) * 32;
    const float* W = a.W[m];
    __half* Wt = wt + a.woff[m];
    int tx = threadIdx.x & 31, ty = threadIdx.x >> 5;   // 32 x 8
    for (int i = ty; i < 32; i += 8)
        tile[i][tx] = W[(size_t)(k0 + i) * N + n0 + tx];
    __syncthreads();
    for (int i = ty; i < 32; i += 8)
        Wt[(size_t)(n0 + i) * K + k0 + tx] = __float2half_rn(tile[tx][i]);
}

// ---------------- preprocessing #2: fused scan + dinv (+ re-zero degi) -----
__global__ void __launch_bounds__(1024) k_scan_all(
    int* __restrict__ deg, float* __restrict__ dinv,
    int* __restrict__ rowptr, int* __restrict__ cursor, int n, int e) {
    __shared__ int sh[1024];
    int t = threadIdx.x;
    int per = (n + 1023) >> 10;
    int lo = t * per, hi = min(lo + per, n);
    int sum = 0;
    for (int i = lo; i < hi; i++) sum += deg[i];
    sh[t] = sum;
    __syncthreads();
    for (int o = 1; o < 1024; o <<= 1) {
        int u = (t >= o) ? sh[t - o] : 0;
        __syncthreads();
        sh[t] += u;
        __syncthreads();
    }
    int off = sh[t] - sum;
    for (int i = lo; i < hi; i++) {
        int d = deg[i];
        deg[i] = 0;
        rowptr[i] = off;
        cursor[i] = off;
        dinv[i] = rsqrtf((float)d + 1.0f);
        off += d;
    }
    if (t == 0) rowptr[n] = e;
}

// ---------------- preprocessing #3: bucket edges by dst --------------------
__global__ void k_bucket(const int* __restrict__ src, const int* __restrict__ dst,
                         const float* __restrict__ dinv, int* __restrict__ cursor,
                         int* __restrict__ esrc, float* __restrict__ enorm, int e) {
    int i = blockIdx.x * blockDim.x + threadIdx.x;
    if (i < e) {
        int s = src[i], d = dst[i];
        int pos = atomicAdd(&cursor[d], 1);
        esrc[pos] = s;
        enorm[pos] = dinv[s] * dinv[d];
    }
}

// ---------------- FP16 tensor-core GEMM: 128x128 tile, 2-stage -------------
// C = A[M,K] @ Bt^T; A,Bt half. K%32==0, N%128==0.
// 8 warps (4 M x 2 N), warp tile 32x64, m16n8k16. 2 CTAs/SM.
// MODE 0: half Ch = raw.  MODE 1: half Ch = C + bias + addH.  MODE 2: half Ch = gelu(C+bias).
#define HPITCH 40                              // halves per row (32 data + 8 pad)
#define H_A_STAGE (128 * HPITCH)
#define H_B_STAGE (128 * HPITCH)
#define H_STAGE   (H_A_STAGE + H_B_STAGE)
#define H_SMEM_BYTES (2 * H_STAGE * 2)         // 40960

template <int MODE>
__global__ void __launch_bounds__(256, 2) gemm_h(
    const __half* __restrict__ A, const __half* __restrict__ Bt,
    __half* __restrict__ Ch,
    int M, int K, int N, const float* __restrict__ bias, const __half* __restrict__ addH) {
    extern __shared__ __half smh[];
    const uint32_t smem_u32 = (uint32_t)__cvta_generic_to_shared(smh);

    const int tid  = threadIdx.x;
    const int lane = tid & 31;
    const int wid  = tid >> 5;
    const int wm = wid & 3, wn = wid >> 2;
    const int gid = lane >> 2, tig = lane & 3;
    const int row0 = blockIdx.y * 128;
    const int col0 = blockIdx.x * 128;

    const int lr[2] = {(tid + 0) >> 2, (tid + 256) >> 2};
    const int lc = (tid & 3) * 8;

    const int k_tiles = K >> 5;

    auto load_stage = [&](int s, int k0) {
        __half* as = smh + s * H_STAGE;
        __half* bs = as + H_A_STAGE;
        #pragma unroll
        for (int i = 0; i < 2; i++) {
            int row = lr[i];
            int grow = row0 + row;
            int ok = (grow < M) ? 16 : 0;
            if (!ok) grow = M - 1;
            cp16(&as[row * HPITCH + lc], &A[(size_t)grow * K + k0 + lc], ok);
        }
        #pragma unroll
        for (int i = 0; i < 2; i++) {
            int n = lr[i];
            cp16(&bs[n * HPITCH + lc], &Bt[(size_t)(col0 + n) * K + k0 + lc], 16);
        }
    };

    const uint32_t a_off = ((uint32_t)((wm * 32 + (lane & 15)) * HPITCH + (lane >> 4) * 8)) * 2u;
    const uint32_t b_off = ((uint32_t)((wn * 64 + (lane & 7)) * HPITCH + ((lane >> 3) & 1) * 8)) * 2u;

    float acc[2][8][4];
    #pragma unroll
    for (int i = 0; i < 2; i++)
        #pragma unroll
        for (int j = 0; j < 8; j++)
            #pragma unroll
            for (int k = 0; k < 4; k++) acc[i][j][k] = 0.0f;

    load_stage(0, 0);
    cp_commit();

    for (int t = 0; t < k_tiles; t++) {
        cp_wait<0>();
        __syncthreads();
        const int st = t & 1;
        if (t + 1 < k_tiles) load_stage((t + 1) & 1, (t + 1) * 32);
        cp_commit();

        const uint32_t as_base = smem_u32 + (uint32_t)(st * H_STAGE) * 2u;
        const uint32_t bs_base = as_base + (uint32_t)H_A_STAGE * 2u;

        #pragma unroll
        for (int ks = 0; ks < 2; ks++) {
            uint32_t af[2][4], bf[8][2];
            #pragma unroll
            for (int mt = 0; mt < 2; mt++)
                ldsm_x4(af[mt], as_base + a_off + (uint32_t)(mt * 16 * HPITCH + ks * 16) * 2u);
            #pragma unroll
            for (int nt = 0; nt < 8; nt++)
                ldsm_x2(bf[nt], bs_base + b_off + (uint32_t)(nt * 8 * HPITCH + ks * 16) * 2u);
            #pragma unroll
            for (int mt = 0; mt < 2; mt++)
                #pragma unroll
                for (int nt = 0; nt < 8; nt++)
                    mma_f16(acc[mt][nt], af[mt], bf[nt]);
        }
    }

    #pragma unroll
    for (int mt = 0; mt < 2; mt++) {
        #pragma unroll
        for (int half_ = 0; half_ < 2; half_++) {
            int row = row0 + wm * 32 + mt * 16 + gid + half_ * 8;
            if (row >= M) continue;
            #pragma unroll
            for (int nt = 0; nt < 8; nt++) {
                int col = col0 + wn * 64 + nt * 8 + tig * 2;
                float v0 = acc[mt][nt][half_ * 2 + 0];
                float v1 = acc[mt][nt][half_ * 2 + 1];
                size_t o = (size_t)row * N + col;
                if (MODE == 1) {
                    __half2 av = *(const __half2*)&addH[o];
                    v0 += bias[col]     + __half2float(av.x);
                    v1 += bias[col + 1] + __half2float(av.y);
                } else if (MODE == 2) {
                    v0 = gelu_exact(v0 + bias[col]);
                    v1 = gelu_exact(v1 + bias[col + 1]);
                }
                *(__half2*)&Ch[o] = __floats2half2_rn(v0, v1);
            }
        }
    }
}

// ---------------- FP16 small GEMM (N=64 logits), 2-stage, fp32 out ---------
#define HS_A_STAGE (128 * HPITCH)
#define HS_B_STAGE (64 * HPITCH)
#define HS_STAGE   (HS_A_STAGE + HS_B_STAGE)
#define HS_SMEM_BYTES (2 * HS_STAGE * 2)       // 30720

__global__ void __launch_bounds__(256) gemm_small_h(
    const __half* __restrict__ A, const __half* __restrict__ Bt, float* __restrict__ C,
    int M, int K, int N) {
    extern __shared__ __half smh[];
    const uint32_t smem_u32 = (uint32_t)__cvta_generic_to_shared(smh);

    const int tid  = threadIdx.x;
    const int lane = tid & 31;
    const int wid  = tid >> 5;
    const int wm = wid & 3, wn = wid >> 2;
    const int gid = lane >> 2, tig = lane & 3;
    const int row0 = blockIdx.y * 128;

    const int lr[2] = {(tid + 0) >> 2, (tid + 256) >> 2};
    const int lc = (tid & 3) * 8;
    const int bn = tid >> 2;
    const int k_tiles = K >> 5;

    auto load_stage = [&](int s, int k0) {
        __half* as = smh + s * HS_STAGE;
        __half* bs = as + HS_A_STAGE;
        #pragma unroll
        for (int i = 0; i < 2; i++) {
            int row = lr[i];
            int grow = row0 + row;
            int ok = (grow < M) ? 16 : 0;
            if (!ok) grow = M - 1;
            cp16(&as[row * HPITCH + lc], &A[(size_t)grow * K + k0 + lc], ok);
        }
        if (bn < 64)
            cp16(&bs[bn * HPITCH + lc], &Bt[(size_t)bn * K + k0 + lc], 16);
    };

    const uint32_t a_off = ((uint32_t)((wm * 32 + (lane & 15)) * HPITCH + (lane >> 4) * 8)) * 2u;
    const uint32_t b_off = ((uint32_t)((wn * 32 + (lane & 7)) * HPITCH + ((lane >> 3) & 1) * 8)) * 2u;

    float acc[2][4][4];
    #pragma unroll
    for (int i = 0; i < 2; i++)
        #pragma unroll
        for (int j = 0; j < 4; j++)
            #pragma unroll
            for (int k = 0; k < 4; k++) acc[i][j][k] = 0.0f;

    load_stage(0, 0);
    cp_commit();

    for (int t = 0; t < k_tiles; t++) {
        cp_wait<0>();
        __syncthreads();
        const int st = t & 1;
        if (t + 1 < k_tiles) load_stage((t + 1) & 1, (t + 1) * 32);
        cp_commit();

        const uint32_t as_base = smem_u32 + (uint32_t)(st * HS_STAGE) * 2u;
        const uint32_t bs_base = as_base + (uint32_t)HS_A_STAGE * 2u;

        #pragma unroll
        for (int ks = 0; ks < 2; ks++) {
            uint32_t af[2][4], bf[4][2];
            #pragma unroll
            for (int mt = 0; mt < 2; mt++)
                ldsm_x4(af[mt], as_base + a_off + (uint32_t)(mt * 16 * HPITCH + ks * 16) * 2u);
            #pragma unroll
            for (int nt = 0; nt < 4; nt++)
                ldsm_x2(bf[nt], bs_base + b_off + (uint32_t)(nt * 8 * HPITCH + ks * 16) * 2u);
            #pragma unroll
            for (int mt = 0; mt < 2; mt++)
                #pragma unroll
                for (int nt = 0; nt < 4; nt++)
                    mma_f16(acc[mt][nt], af[mt], bf[nt]);
        }
    }

    #pragma unroll
    for (int mt = 0; mt < 2; mt++) {
        #pragma unroll
        for (int half_ = 0; half_ < 2; half_++) {
            int row = row0 + wm * 32 + mt * 16 + gid + half_ * 8;
            if (row >= M) continue;
            #pragma unroll
            for (int nt = 0; nt < 4; nt++) {
                int col = wn * 32 + nt * 8 + tig * 2;
                size_t o = (size_t)row * N + col;
                *(float2*)&C[o] = make_float2(acc[mt][nt][half_ * 2 + 0],
                                              acc[mt][nt][half_ * 2 + 1]);
            }
        }
    }
}

// ---------------- fused gather + conv-epilogue + LN + GELU (half I/O) ------
// Gathers HALF rows of hw (512B/row), accumulates fp32; writes hH + skipH.
__global__ void __launch_bounds__(256) gcn_post(
    const __half* __restrict__ hw, const __half* __restrict__ pp,
    const int* __restrict__ rowptr, const int* __restrict__ esrc,
    const float* __restrict__ enorm, const float* __restrict__ dinv,
    const float* __restrict__ bcv, const float* __restrict__ bpv,
    const float* __restrict__ gv, const float* __restrict__ bev,
    __half* __restrict__ skipH_out, __half* __restrict__ hH_out) {
    int r = blockIdx.x;
    int tid = threadIdx.x;
    int g = tid & 63;
    int e = tid >> 6;
    int lane = tid & 31;
    int warp = tid >> 5;
    int beg = rowptr[r], end = rowptr[r + 1];

    float4 acc = make_float4(0.f, 0.f, 0.f, 0.f);
    for (int j = beg + e; j < end; j += 4) {
        int s = __ldg(&esrc[j]);
        float w = __ldg(&enorm[j]);
        const __half2* hp = (const __half2*)&hw[(size_t)s * 256 + g * 4];
        float2 fa = __half22float2(hp[0]);
        float2 fb = __half22float2(hp[1]);
        acc.x = fmaf(fa.x, w, acc.x);
        acc.y = fmaf(fa.y, w, acc.y);
        acc.z = fmaf(fb.x, w, acc.z);
        acc.w = fmaf(fb.y, w, acc.w);
    }
    __shared__ float4 sacc[256];
    sacc[tid] = acc;
    __syncthreads();

    float4 t = make_float4(0.f, 0.f, 0.f, 0.f);
    float partial = 0.f;
    size_t base = (size_t)r * 256 + g * 4;
    if (tid < 64) {
        float4 a0 = sacc[g], a1 = sacc[g + 64], a2 = sacc[g + 128], a3 = sacc[g + 192];
        float ax = a0.x + a1.x + a2.x + a3.x;
        float ay = a0.y + a1.y + a2.y + a3.y;
        float az = a0.z + a1.z + a2.z + a3.z;
        float aw = a0.w + a1.w + a2.w + a3.w;
        float di = dinv[r];
        float d2 = di * di;
        const __half2* hp = (const __half2*)&hw[base];
        const __half2* ppp = (const __half2*)&pp[base];
        float2 h0 = __half22float2(hp[0]), h1 = __half22float2(hp[1]);
        float2 p0 = __half22float2(ppp[0]), p1 = __half22float2(ppp[1]);
        float4 bc4 = *(const float4*)&bcv[g * 4];
        float4 bp4 = *(const float4*)&bpv[g * 4];
        t.x = ax + d2 * h0.x + bc4.x + p0.x + bp4.x;
        t.y = ay + d2 * h0.y + bc4.y + p0.y + bp4.y;
        t.z = az + d2 * h1.x + bc4.z + p1.x + bp4.z;
        t.w = aw + d2 * h1.y + bc4.w + p1.y + bp4.w;
        __half2* sh = (__half2*)&skipH_out[base];
        sh[0] = __floats2half2_rn(t.x, t.y);
        sh[1] = __floats2half2_rn(t.z, t.w);
        partial = t.x + t.y + t.z + t.w;
    }

    __shared__ float red[8];
    float s = partial;
    #pragma unroll
    for (int o = 16; o > 0; o >>= 1) s += __shfl_xor_sync(0xffffffffu, s, o);
    if (lane == 0) red[warp] = s;
    __syncthreads();
    float m = 0.f;
    #pragma unroll
    for (int i = 0; i < 8; i++) m += red[i];
    m *= (1.0f / 256.0f);
    __syncthreads();

    float vpart = 0.f;
    float dx = 0.f, dy = 0.f, dz = 0.f, dw = 0.f;
    if (tid < 64) {
        dx = t.x - m; dy = t.y - m; dz = t.z - m; dw = t.w - m;
        vpart = dx * dx + dy * dy + dz * dz + dw * dw;
    }
    float sv = vpart;
    #pragma unroll
    for (int o = 16; o > 0; o >>= 1) sv += __shfl_xor_sync(0xffffffffu, sv, o);
    if (lane == 0) red[warp] = sv;
    __syncthreads();
    float var = 0.f;
    #pragma unroll
    for (int i = 0; i < 8; i++) var += red[i];
    var *= (1.0f / 256.0f);

    if (tid < 64) {
        float rs = rsqrtf(var + 1e-5f);
        float4 g4 = *(const float4*)&gv[g * 4];
        float4 b4 = *(const float4*)&bev[g * 4];
        float yx = gelu_exact(dx * rs * g4.x + b4.x);
        float yy = gelu_exact(dy * rs * g4.y + b4.y);
        float yz = gelu_exact(dz * rs * g4.z + b4.z);
        float yw = gelu_exact(dw * rs * g4.w + b4.w);
        __half2* hh = (__half2*)&hH_out[base];
        hh[0] = __floats2half2_rn(yx, yy);
        hh[1] = __floats2half2_rn(yz, yw);
    }
}

// ---------------- log-softmax over 64 logits -------------------------------
__global__ void k_logsoftmax(const float* __restrict__ logits, const float* __restrict__ bf2,
                             float* __restrict__ out, int Nn) {
    int r = blockIdx.x * 8 + (threadIdx.x >> 5);
    int lane = threadIdx.x & 31;
    if (r >= Nn) return;
    float v0 = logits[(size_t)r * 64 + lane]      + bf2[lane];
    float v1 = logits[(size_t)r * 64 + 32 + lane] + bf2[32 + lane];
    float mx = fmaxf(v0, v1);
    #pragma unroll
    for (int o = 16; o > 0; o >>= 1) mx = fmaxf(mx, __shfl_xor_sync(0xffffffffu, mx, o));
    float s = expf(v0 - mx) + expf(v1 - mx);
    #pragma unroll
    for (int o = 16; o > 0; o >>= 1) s += __shfl_xor_sync(0xffffffffu, s, o);
    float ls = logf(s);
    out[(size_t)r * 64 + lane]      = v0 - mx - ls;
    out[(size_t)r * 64 + 32 + lane] = v1 - mx - ls;
}

// ---------------- launch ---------------------------------------------------
extern "C" void kernel_launch(void* const* d_in, const int* in_sizes, int n_in,
                              void* d_out, int out_size) {
    const float* x  = (const float*)d_in[0];
    const int*   ei = (const int*)d_in[1];
    int E  = in_sizes[1] / 2;
    int Nn = in_sizes[0] / 128;
    const int* src = ei;
    const int* dst = ei + E;

    const float* Wc[3] = {(const float*)d_in[2],  (const float*)d_in[8],  (const float*)d_in[14]};
    const float* bc[3] = {(const float*)d_in[3],  (const float*)d_in[9],  (const float*)d_in[15]};
    const float* Wp[3] = {(const float*)d_in[4],  (const float*)d_in[10], (const float*)d_in[16]};
    const float* bp[3] = {(const float*)d_in[5],  (const float*)d_in[11], (const float*)d_in[17]};
    const float* gg[3] = {(const float*)d_in[6],  (const float*)d_in[12], (const float*)d_in[18]};
    const float* be[3] = {(const float*)d_in[7],  (const float*)d_in[13], (const float*)d_in[19]};
    const float* W_in = (const float*)d_in[20];
    const float* b_in = (const float*)d_in[21];
    const float* Wf1  = (const float*)d_in[22];
    const float* bf1  = (const float*)d_in[23];
    const float* Wf2  = (const float*)d_in[24];
    const float* bf2  = (const float*)d_in[25];
    float* out = (float*)d_out;

    float *pLog, *pDinv, *pEn;
    __half *pXh, *pHh, *pSkipH, *pHwH, *pPH, *pResH, *pF1H, *pWtH;
    int *pDegi, *pRp, *pCur, *pEs;
    cudaGetSymbolAddress((void**)&pLog,  g_logits);
    cudaGetSymbolAddress((void**)&pXh,   g_xh);
    cudaGetSymbolAddress((void**)&pHh,   g_hH);
    cudaGetSymbolAddress((void**)&pSkipH,g_skipH);
    cudaGetSymbolAddress((void**)&pHwH,  g_hwH);
    cudaGetSymbolAddress((void**)&pPH,   g_pH);
    cudaGetSymbolAddress((void**)&pResH, g_resH);
    cudaGetSymbolAddress((void**)&pF1H,  g_f1H);
    cudaGetSymbolAddress((void**)&pWtH,  g_wtH);
    cudaGetSymbolAddress((void**)&pDinv, g_dinv);
    cudaGetSymbolAddress((void**)&pDegi, g_degi);
    cudaGetSymbolAddress((void**)&pRp,   g_rowptr);
    cudaGetSymbolAddress((void**)&pCur,  g_cursor);
    cudaGetSymbolAddress((void**)&pEs,   g_esrc);
    cudaGetSymbolAddress((void**)&pEn,   g_enorm);

    TransArgs ta;
    const float* Ws[9] = {Wc[0], Wp[0], Wc[1], Wp[1], Wc[2], Wp[2], W_in, Wf1, Wf2};
    int Ks[9]  = {128, 128, 256, 256, 256, 256, 128, 256, 512};
    int Nss[9] = {256, 256, 256, 256, 256, 256, 256, 512, 64};
    long long woff[9] = {0, 32768, 65536, 131072, 196608, 262144, 327680, 360448, 491520};
    int total_tiles = 0;
    for (int i = 0; i < 9; i++) {
        ta.W[i] = Ws[i];
        ta.K[i] = Ks[i];
        ta.N[i] = Nss[i];
        ta.woff[i] = woff[i];
        ta.tiles[i] = (Ks[i] >> 5) * (Nss[i] >> 5);
        total_tiles += ta.tiles[i];
    }

    // --- preprocessing: 3 kernels (first GEMM = launch #4, profiled) ---
    int cblocks = (E + 255) / 256;
    int xcount  = Nn * 128;
    int xblocks = (xcount + 255) / 256;
    k_count_transpose<<<cblocks + total_tiles + xblocks, 256>>>(
        ta, pWtH, pXh, x, pDegi, dst, E, cblocks, total_tiles, xcount);
    k_scan_all<<<1, 1024>>>(pDegi, pDinv, pRp, pCur, Nn, E);
    k_bucket<<<(E + 255) / 256, 256>>>(src, dst, pDinv, pCur, pEs, pEn, E);

    int gy = (Nn + 127) / 128;

    // --- 3 GCN layers (layer 0: h == skip == x) ---
    const __half* hA    = pXh;
    const __half* skipA = pXh;
    int Kin = 128;
    for (int l = 0; l < 3; l++) {
        gemm_h<0><<<dim3(2, gy), 256, H_SMEM_BYTES>>>(hA,    pWtH + woff[2 * l],     pHwH, Nn, Kin, 256, nullptr, nullptr);
        gemm_h<0><<<dim3(2, gy), 256, H_SMEM_BYTES>>>(skipA, pWtH + woff[2 * l + 1], pPH,  Nn, Kin, 256, nullptr, nullptr);
        gcn_post<<<Nn, 256>>>(pHwH, pPH, pRp, pEs, pEn, pDinv,
                              bc[l], bp[l], gg[l], be[l], pSkipH, pHh);
        hA = pHh; skipA = pSkipH; Kin = 256;
    }

    // --- long residual (fused epilogue) + MLP head ---
    gemm_h<1><<<dim3(2, gy), 256, H_SMEM_BYTES>>>(pXh, pWtH + woff[6], pResH, Nn, 128, 256, b_in, pHh);
    gemm_h<2><<<dim3(4, gy), 256, H_SMEM_BYTES>>>(pResH, pWtH + woff[7], pF1H, Nn, 256, 512, bf1, nullptr);
    gemm_small_h<<<dim3(1, gy), 256, HS_SMEM_BYTES>>>(pF1H, pWtH + woff[8], pLog, Nn, 512, 64);
    k_logsoftmax<<<(Nn + 7) / 8, 256>>>(pLog, bf2, out, Nn);
}